// round 3
// baseline (speedup 1.0000x reference)
#include <cuda_runtime.h>
#include <cuda_bf16.h>
#include <math.h>

#define D_   1024
#define U_   2048
#define R_   256
#define L_   1024
#define M_   512
#define QL   2304   // U + R
#define KVL  3840   // M + R + L + U
#define NH   16
#define HD   64

// Scratch (static device allocations are the sanctioned scratch mechanism)
__device__ float g_query[(size_t)QL * D_];
__device__ float g_attn[(size_t)QL * D_];

// ---------------------------------------------------------------------------
// Shared SGEMM mainloop: C(64x64) tile of A(row-major, K contig) @ B(row-major,
// K contig)^T. BK=16, 256 threads, 4x4 microtile per thread.
// ---------------------------------------------------------------------------
__device__ __forceinline__ void gemm_mainloop(const float* __restrict__ aptr,
                                              const float* __restrict__ bptr,
                                              float (*As)[68], float (*Bs)[68],
                                              int tid, float acc[16]) {
    const int lrow = tid >> 2;        // 0..63
    const int lseg = (tid & 3) * 4;   // 0,4,8,12
    const int m0 = (tid & 15) * 4;
    const int n0 = (tid >> 4) * 4;
    for (int kt = 0; kt < D_; kt += 16) {
        float4 av = *(const float4*)(aptr + kt + lseg);
        float4 bv = *(const float4*)(bptr + kt + lseg);
        __syncthreads();
        As[lseg + 0][lrow] = av.x; As[lseg + 1][lrow] = av.y;
        As[lseg + 2][lrow] = av.z; As[lseg + 3][lrow] = av.w;
        Bs[lseg + 0][lrow] = bv.x; Bs[lseg + 1][lrow] = bv.y;
        Bs[lseg + 2][lrow] = bv.z; Bs[lseg + 3][lrow] = bv.w;
        __syncthreads();
#pragma unroll
        for (int k = 0; k < 16; k++) {
            float4 a4 = *(const float4*)&As[k][m0];
            float4 b4 = *(const float4*)&Bs[k][n0];
            float a[4] = {a4.x, a4.y, a4.z, a4.w};
            float b[4] = {b4.x, b4.y, b4.z, b4.w};
#pragma unroll
            for (int i = 0; i < 4; i++)
#pragma unroll
                for (int j = 0; j < 4; j++)
                    acc[i * 4 + j] = fmaf(a[i], b[j], acc[i * 4 + j]);
        }
    }
}

// query = concat(right_context, utterance) @ Wq^T + bq  -> g_query
__global__ __launch_bounds__(256) void gemm_q_kernel(const float* __restrict__ rc,
                                                     const float* __restrict__ utt,
                                                     const float* __restrict__ W,
                                                     const float* __restrict__ bias) {
    __shared__ __align__(16) float As[16][68];
    __shared__ __align__(16) float Bs[16][68];
    const int tid = threadIdx.x;
    const int bm = blockIdx.x * 64, bn = blockIdx.y * 64;
    const int lrow = tid >> 2;
    const int arow = bm + lrow;
    const float* aptr = (arow < R_) ? rc + (size_t)arow * D_
                                    : utt + (size_t)(arow - R_) * D_;
    const float* bptr = W + (size_t)(bn + lrow) * D_;
    float acc[16] = {};
    gemm_mainloop(aptr, bptr, As, Bs, tid, acc);
    const int m0 = (tid & 15) * 4, n0 = (tid >> 4) * 4;
    float4 bb = *(const float4*)(bias + bn + n0);
#pragma unroll
    for (int i = 0; i < 4; i++) {
        *(float4*)(g_query + (size_t)(bm + m0 + i) * D_ + bn + n0) =
            make_float4(acc[i*4+0] + bb.x, acc[i*4+1] + bb.y,
                        acc[i*4+2] + bb.z, acc[i*4+3] + bb.w);
    }
}

// kv = concat(memory, right_context, utterance) @ Wkv^T + bkv
// Scattered directly into key/value output buffers with left-context gap.
__global__ __launch_bounds__(256) void gemm_kv_kernel(const float* __restrict__ mem,
                                                      const float* __restrict__ rc,
                                                      const float* __restrict__ utt,
                                                      const float* __restrict__ W,
                                                      const float* __restrict__ bias,
                                                      float* __restrict__ keyBuf,
                                                      float* __restrict__ valBuf) {
    __shared__ __align__(16) float As[16][68];
    __shared__ __align__(16) float Bs[16][68];
    const int tid = threadIdx.x;
    const int bm = blockIdx.x * 64, bn = blockIdx.y * 64;
    const int lrow = tid >> 2;
    const int arow = bm + lrow;
    const float* aptr = (arow < M_)      ? mem + (size_t)arow * D_
                      : (arow < M_ + R_) ? rc + (size_t)(arow - M_) * D_
                                         : utt + (size_t)(arow - M_ - R_) * D_;
    const float* bptr = W + (size_t)(bn + lrow) * D_;
    float acc[16] = {};
    gemm_mainloop(aptr, bptr, As, Bs, tid, acc);
    const int m0 = (tid & 15) * 4, n0 = (tid >> 4) * 4;
    float4 bb = *(const float4*)(bias + bn + n0);
    float* obase = (bn < D_) ? keyBuf : valBuf;
    const int ncol = (bn < D_) ? (bn + n0) : (bn - D_ + n0);
#pragma unroll
    for (int i = 0; i < 4; i++) {
        int row = bm + m0 + i;
        int ro = (row < M_ + R_) ? row : row + L_;  // left-context inserted at 768
        *(float4*)(obase + (size_t)ro * D_ + ncol) =
            make_float4(acc[i*4+0] + bb.x, acc[i*4+1] + bb.y,
                        acc[i*4+2] + bb.z, acc[i*4+3] + bb.w);
    }
}

// out = g_attn @ Wo^T + bo -> outBuf
__global__ __launch_bounds__(256) void gemm_o_kernel(const float* __restrict__ W,
                                                     const float* __restrict__ bias,
                                                     float* __restrict__ outBuf) {
    __shared__ __align__(16) float As[16][68];
    __shared__ __align__(16) float Bs[16][68];
    const int tid = threadIdx.x;
    const int bm = blockIdx.x * 64, bn = blockIdx.y * 64;
    const int lrow = tid >> 2;
    const float* aptr = g_attn + (size_t)(bm + lrow) * D_;
    const float* bptr = W + (size_t)(bn + lrow) * D_;
    float acc[16] = {};
    gemm_mainloop(aptr, bptr, As, Bs, tid, acc);
    const int m0 = (tid & 15) * 4, n0 = (tid >> 4) * 4;
    float4 bb = *(const float4*)(bias + bn + n0);
#pragma unroll
    for (int i = 0; i < 4; i++) {
        *(float4*)(outBuf + (size_t)(bm + m0 + i) * D_ + bn + n0) =
            make_float4(acc[i*4+0] + bb.x, acc[i*4+1] + bb.y,
                        acc[i*4+2] + bb.z, acc[i*4+3] + bb.w);
    }
}

// ---------------------------------------------------------------------------
// Flash attention fp32: block = (64 q-rows) x (one head), 256 threads.
// Thread t owns q-row r=t/4 and 16 columns/dims (group c4=t%4).
// Smem tiles padded to 68 floats/row (16B-aligned float4, conflict-light).
// KPs buffer holds K tile during S-phase, then P (probs) for the O-phase.
// ---------------------------------------------------------------------------
__global__ __launch_bounds__(256) void attn_kernel(const float* __restrict__ Kg,
                                                   const float* __restrict__ Vg) {
    extern __shared__ __align__(16) float sm[];
    float* Qs  = sm;                 // [64][68]
    float* KPs = sm + 64 * 68;       // [64][68] K then P
    float* Vs  = sm + 2 * 64 * 68;   // [64][68]
    const int tid = threadIdx.x;
    const int r = tid >> 2;
    const int cbase = (tid & 3) * 16;
    const int qbase = blockIdx.x * 64;
    const int hoff = blockIdx.y * HD;

    // Load Q tile (pre-scaled by 1/sqrt(64))
#pragma unroll
    for (int j = 0; j < 4; j++) {
        int id = j * 256 + tid;
        int row = id >> 4;
        int seg = (id & 15) * 4;
        float4 v = *(const float4*)(g_query + (size_t)(qbase + row) * D_ + hoff + seg);
        *(float4*)(Qs + row * 68 + seg) =
            make_float4(v.x * 0.125f, v.y * 0.125f, v.z * 0.125f, v.w * 0.125f);
    }

    float acc[16];
#pragma unroll
    for (int i = 0; i < 16; i++) acc[i] = 0.f;
    float m_run = -INFINITY, l_run = 0.f;

    for (int kt = 0; kt < KVL; kt += 64) {
        __syncthreads();  // previous O-phase reads of KPs/Vs done
#pragma unroll
        for (int j = 0; j < 4; j++) {
            int id = j * 256 + tid;
            int row = id >> 4;
            int seg = (id & 15) * 4;
            *(float4*)(KPs + row * 68 + seg) =
                *(const float4*)(Kg + (size_t)(kt + row) * D_ + hoff + seg);
            *(float4*)(Vs + row * 68 + seg) =
                *(const float4*)(Vg + (size_t)(kt + row) * D_ + hoff + seg);
        }
        __syncthreads();

        // S = Q @ K^T (16 columns per thread)
        float s[16];
#pragma unroll
        for (int i = 0; i < 16; i++) s[i] = 0.f;
        for (int dseg = 0; dseg < 64; dseg += 4) {
            float4 q4 = *(const float4*)(Qs + r * 68 + dseg);
#pragma unroll
            for (int i = 0; i < 16; i++) {
                float4 k4 = *(const float4*)(KPs + (cbase + i) * 68 + dseg);
                s[i] = fmaf(q4.x, k4.x, s[i]);
                s[i] = fmaf(q4.y, k4.y, s[i]);
                s[i] = fmaf(q4.z, k4.z, s[i]);
                s[i] = fmaf(q4.w, k4.w, s[i]);
            }
        }

        // Online softmax (row spread over 4 consecutive lanes)
        float mt = s[0];
#pragma unroll
        for (int i = 1; i < 16; i++) mt = fmaxf(mt, s[i]);
        mt = fmaxf(mt, __shfl_xor_sync(0xffffffffu, mt, 1));
        mt = fmaxf(mt, __shfl_xor_sync(0xffffffffu, mt, 2));
        float mnew = fmaxf(m_run, mt);
        float alpha = __expf(m_run - mnew);  // exp(-inf)=0 on first tile
        float ls = 0.f;
#pragma unroll
        for (int i = 0; i < 16; i++) { s[i] = __expf(s[i] - mnew); ls += s[i]; }
        ls += __shfl_xor_sync(0xffffffffu, ls, 1);
        ls += __shfl_xor_sync(0xffffffffu, ls, 2);
        l_run = l_run * alpha + ls;
        m_run = mnew;
#pragma unroll
        for (int i = 0; i < 16; i++) acc[i] *= alpha;

        __syncthreads();  // everyone done reading K from KPs
#pragma unroll
        for (int i = 0; i < 16; i++) KPs[r * 68 + cbase + i] = s[i];
        __syncthreads();

        // O += P @ V (thread owns dims [cbase, cbase+16))
        for (int kv = 0; kv < 64; kv++) {
            float p = KPs[r * 68 + kv];
#pragma unroll
            for (int q = 0; q < 4; q++) {
                float4 v4 = *(const float4*)(Vs + kv * 68 + cbase + q * 4);
                acc[q * 4 + 0] = fmaf(p, v4.x, acc[q * 4 + 0]);
                acc[q * 4 + 1] = fmaf(p, v4.y, acc[q * 4 + 1]);
                acc[q * 4 + 2] = fmaf(p, v4.z, acc[q * 4 + 2]);
                acc[q * 4 + 3] = fmaf(p, v4.w, acc[q * 4 + 3]);
            }
        }
    }

    float inv = 1.0f / l_run;
    float* op = g_attn + (size_t)(qbase + r) * D_ + hoff + cbase;
#pragma unroll
    for (int q = 0; q < 4; q++) {
        *(float4*)(op + q * 4) = make_float4(acc[q*4+0] * inv, acc[q*4+1] * inv,
                                             acc[q*4+2] * inv, acc[q*4+3] * inv);
    }
}

// ---------------------------------------------------------------------------
extern "C" void kernel_launch(void* const* d_in, const int* in_sizes, int n_in,
                              void* d_out, int out_size) {
    const float* utt = (const float*)d_in[0];
    const float* rc  = (const float*)d_in[1];
    const float* mem = (const float*)d_in[2];
    const float* lck = (const float*)d_in[3];
    const float* lcv = (const float*)d_in[4];
    const float* Wq  = (const float*)d_in[5];
    const float* bq  = (const float*)d_in[6];
    const float* Wkv = (const float*)d_in[7];
    const float* bkv = (const float*)d_in[8];
    const float* Wo  = (const float*)d_in[9];
    const float* bo  = (const float*)d_in[10];

    float* outBuf = (float*)d_out;                       // [2304,1024]
    float* keyBuf = outBuf + (size_t)QL * D_;            // [3840,1024]
    float* valBuf = keyBuf + (size_t)KVL * D_;           // [3840,1024]

    constexpr int ATTN_SMEM = 3 * 64 * 68 * (int)sizeof(float);  // 52224 B
    cudaFuncSetAttribute(attn_kernel, cudaFuncAttributeMaxDynamicSharedMemorySize,
                         ATTN_SMEM);

    gemm_q_kernel<<<dim3(QL / 64, D_ / 64), 256>>>(rc, utt, Wq, bq);
    gemm_kv_kernel<<<dim3((M_ + R_ + U_) / 64, 2 * D_ / 64), 256>>>(
        mem, rc, utt, Wkv, bkv, keyBuf, valBuf);
    cudaMemcpyAsync(keyBuf + (size_t)(M_ + R_) * D_, lck,
                    (size_t)L_ * D_ * sizeof(float), cudaMemcpyDeviceToDevice);
    cudaMemcpyAsync(valBuf + (size_t)(M_ + R_) * D_, lcv,
                    (size_t)L_ * D_ * sizeof(float), cudaMemcpyDeviceToDevice);
    attn_kernel<<<dim3(QL / 64, NH), 256, ATTN_SMEM>>>(keyBuf, valBuf);
    gemm_o_kernel<<<dim3(QL / 64, D_ / 64), 256>>>(Wo, bo, outBuf);
}

// round 5
// speedup vs baseline: 3.1128x; 3.1128x over previous
#include <cuda_runtime.h>
#include <cuda_bf16.h>
#include <math.h>

#define D_   1024
#define U_   2048
#define R_   256
#define L_   1024
#define M_   512
#define QL   2304   // U + R
#define KVL  3840   // M + R + L + U
#define NH   16
#define HD   64

#define TQ   64     // q rows per block
#define TK   128    // kv rows per tile
#define SSTR 65     // smem row stride (65 % 32 == 1 -> conflict-free column walks)

// Scratch (static device allocations are the sanctioned scratch mechanism)
__device__ float g_query[(size_t)QL * D_];
__device__ float g_attn[(size_t)QL * D_];

// ---------------------------------------------------------------------------
// Shared SGEMM mainloop: C(64x64) tile of A(row-major, K contig) @ B(row-major,
// K contig)^T. BK=16, 256 threads, 4x4 microtile per thread.
// ---------------------------------------------------------------------------
__device__ __forceinline__ void gemm_mainloop(const float* __restrict__ aptr,
                                              const float* __restrict__ bptr,
                                              float (*As)[68], float (*Bs)[68],
                                              int tid, float acc[16]) {
    const int lrow = tid >> 2;        // 0..63
    const int lseg = (tid & 3) * 4;   // 0,4,8,12
    const int m0 = (tid & 15) * 4;
    const int n0 = (tid >> 4) * 4;
    for (int kt = 0; kt < D_; kt += 16) {
        float4 av = *(const float4*)(aptr + kt + lseg);
        float4 bv = *(const float4*)(bptr + kt + lseg);
        __syncthreads();
        As[lseg + 0][lrow] = av.x; As[lseg + 1][lrow] = av.y;
        As[lseg + 2][lrow] = av.z; As[lseg + 3][lrow] = av.w;
        Bs[lseg + 0][lrow] = bv.x; Bs[lseg + 1][lrow] = bv.y;
        Bs[lseg + 2][lrow] = bv.z; Bs[lseg + 3][lrow] = bv.w;
        __syncthreads();
#pragma unroll
        for (int k = 0; k < 16; k++) {
            float4 a4 = *(const float4*)&As[k][m0];
            float4 b4 = *(const float4*)&Bs[k][n0];
            float a[4] = {a4.x, a4.y, a4.z, a4.w};
            float b[4] = {b4.x, b4.y, b4.z, b4.w};
#pragma unroll
            for (int i = 0; i < 4; i++)
#pragma unroll
                for (int j = 0; j < 4; j++)
                    acc[i * 4 + j] = fmaf(a[i], b[j], acc[i * 4 + j]);
        }
    }
}

// query = concat(right_context, utterance) @ Wq^T + bq  -> g_query
__global__ __launch_bounds__(256) void gemm_q_kernel(const float* __restrict__ rc,
                                                     const float* __restrict__ utt,
                                                     const float* __restrict__ W,
                                                     const float* __restrict__ bias) {
    __shared__ __align__(16) float As[16][68];
    __shared__ __align__(16) float Bs[16][68];
    const int tid = threadIdx.x;
    const int bm = blockIdx.x * 64, bn = blockIdx.y * 64;
    const int lrow = tid >> 2;
    const int arow = bm + lrow;
    const float* aptr = (arow < R_) ? rc + (size_t)arow * D_
                                    : utt + (size_t)(arow - R_) * D_;
    const float* bptr = W + (size_t)(bn + lrow) * D_;
    float acc[16] = {};
    gemm_mainloop(aptr, bptr, As, Bs, tid, acc);
    const int m0 = (tid & 15) * 4, n0 = (tid >> 4) * 4;
    float4 bb = *(const float4*)(bias + bn + n0);
#pragma unroll
    for (int i = 0; i < 4; i++) {
        *(float4*)(g_query + (size_t)(bm + m0 + i) * D_ + bn + n0) =
            make_float4(acc[i*4+0] + bb.x, acc[i*4+1] + bb.y,
                        acc[i*4+2] + bb.z, acc[i*4+3] + bb.w);
    }
}

// kv = concat(memory, right_context, utterance) @ Wkv^T + bkv
// Scattered directly into key/value output buffers with left-context gap.
__global__ __launch_bounds__(256) void gemm_kv_kernel(const float* __restrict__ mem,
                                                      const float* __restrict__ rc,
                                                      const float* __restrict__ utt,
                                                      const float* __restrict__ W,
                                                      const float* __restrict__ bias,
                                                      float* __restrict__ keyBuf,
                                                      float* __restrict__ valBuf) {
    __shared__ __align__(16) float As[16][68];
    __shared__ __align__(16) float Bs[16][68];
    const int tid = threadIdx.x;
    const int bm = blockIdx.x * 64, bn = blockIdx.y * 64;
    const int lrow = tid >> 2;
    const int arow = bm + lrow;
    const float* aptr = (arow < M_)      ? mem + (size_t)arow * D_
                      : (arow < M_ + R_) ? rc + (size_t)(arow - M_) * D_
                                         : utt + (size_t)(arow - M_ - R_) * D_;
    const float* bptr = W + (size_t)(bn + lrow) * D_;
    float acc[16] = {};
    gemm_mainloop(aptr, bptr, As, Bs, tid, acc);
    const int m0 = (tid & 15) * 4, n0 = (tid >> 4) * 4;
    float4 bb = *(const float4*)(bias + bn + n0);
    float* obase = (bn < D_) ? keyBuf : valBuf;
    const int ncol = (bn < D_) ? (bn + n0) : (bn - D_ + n0);
#pragma unroll
    for (int i = 0; i < 4; i++) {
        int row = bm + m0 + i;
        int ro = (row < M_ + R_) ? row : row + L_;  // left-context inserted at 768
        *(float4*)(obase + (size_t)ro * D_ + ncol) =
            make_float4(acc[i*4+0] + bb.x, acc[i*4+1] + bb.y,
                        acc[i*4+2] + bb.z, acc[i*4+3] + bb.w);
    }
}

// out = g_attn @ Wo^T + bo -> outBuf
__global__ __launch_bounds__(256) void gemm_o_kernel(const float* __restrict__ W,
                                                     const float* __restrict__ bias,
                                                     float* __restrict__ outBuf) {
    __shared__ __align__(16) float As[16][68];
    __shared__ __align__(16) float Bs[16][68];
    const int tid = threadIdx.x;
    const int bm = blockIdx.x * 64, bn = blockIdx.y * 64;
    const int lrow = tid >> 2;
    const float* aptr = g_attn + (size_t)(bm + lrow) * D_;
    const float* bptr = W + (size_t)(bn + lrow) * D_;
    float acc[16] = {};
    gemm_mainloop(aptr, bptr, As, Bs, tid, acc);
    const int m0 = (tid & 15) * 4, n0 = (tid >> 4) * 4;
    float4 bb = *(const float4*)(bias + bn + n0);
#pragma unroll
    for (int i = 0; i < 4; i++) {
        *(float4*)(outBuf + (size_t)(bm + m0 + i) * D_ + bn + n0) =
            make_float4(acc[i*4+0] + bb.x, acc[i*4+1] + bb.y,
                        acc[i*4+2] + bb.z, acc[i*4+3] + bb.w);
    }
}

// ---------------------------------------------------------------------------
// Flash attention v2: block = 64 q-rows x one head, 256 threads, kv tile 128.
// S-phase: 4x8 microtile (rows r2+16i, cols c2+16j). O-phase: 4x4 microtile.
// All smem rows stride 65 -> every strided/scalar access pattern conflict-free.
// ---------------------------------------------------------------------------
__global__ __launch_bounds__(256) void attn_kernel(const float* __restrict__ Kg,
                                                   const float* __restrict__ Vg) {
    extern __shared__ __align__(16) float sm[];
    float* Qs = sm;                        // [64][65]
    float* Ks = Qs + TQ * SSTR;            // [128][65]
    float* Vs = Ks + TK * SSTR;            // [128][65]
    float* Ps = Vs + TK * SSTR;            // [64][65]  (only 0..127 cols... rows=64,cols up to 128? -> see note)
    float* alpha_s = Ps + TQ * (2 * SSTR); // [64]
    float* l_s = alpha_s + TQ;             // [64]

    const int tid = threadIdx.x;
    const int qbase = blockIdx.x * TQ;
    const int hoff = blockIdx.y * HD;

    // S-phase mapping
    const int c2 = tid & 15;      // col group: cols c2+16j, j<8
    const int r2 = tid >> 4;      // row group: rows r2+16i, i<4
    // O-phase mapping
    const int ro = tid & 15;      // rows ro+16i, i<4
    const int co = tid >> 4;      // cols co+16j, j<4

    // Load Q tile (pre-scaled by 1/sqrt(64)), rows stride SSTR
#pragma unroll
    for (int jj = 0; jj < 4; jj++) {
        int id = jj * 256 + tid;
        int row = id >> 4;
        int seg = (id & 15) * 4;
        float4 v = *(const float4*)(g_query + (size_t)(qbase + row) * D_ + hoff + seg);
        float* dst = Qs + row * SSTR + seg;
        dst[0] = v.x * 0.125f; dst[1] = v.y * 0.125f;
        dst[2] = v.z * 0.125f; dst[3] = v.w * 0.125f;
    }

    float acc[4][4];
#pragma unroll
    for (int i = 0; i < 4; i++)
#pragma unroll
        for (int j = 0; j < 4; j++) acc[i][j] = 0.f;
    float m_run[4], l_run[4];
#pragma unroll
    for (int i = 0; i < 4; i++) { m_run[i] = -INFINITY; l_run[i] = 0.f; }

    for (int kt = 0; kt < KVL; kt += TK) {
        __syncthreads();  // prev O-phase done with Vs/Ps/alpha_s
        // Load K,V tile: 128 rows x 64 dims each; 8 float4 per thread per tensor
#pragma unroll
        for (int jj = 0; jj < 8; jj++) {
            int id = jj * 256 + tid;
            int row = id >> 4;
            int seg = (id & 15) * 4;
            float4 kv4 = *(const float4*)(Kg + (size_t)(kt + row) * D_ + hoff + seg);
            float* kd = Ks + row * SSTR + seg;
            kd[0] = kv4.x; kd[1] = kv4.y; kd[2] = kv4.z; kd[3] = kv4.w;
            float4 vv4 = *(const float4*)(Vg + (size_t)(kt + row) * D_ + hoff + seg);
            float* vd = Vs + row * SSTR + seg;
            vd[0] = vv4.x; vd[1] = vv4.y; vd[2] = vv4.z; vd[3] = vv4.w;
        }
        __syncthreads();

        // ---- S = Q @ K^T : 4 rows x 8 cols per thread ----
        float s[4][8];
#pragma unroll
        for (int i = 0; i < 4; i++)
#pragma unroll
            for (int j = 0; j < 8; j++) s[i][j] = 0.f;
#pragma unroll 4
        for (int d = 0; d < HD; d++) {
            float qf[4], kf[8];
#pragma unroll
            for (int i = 0; i < 4; i++) qf[i] = Qs[(r2 + 16 * i) * SSTR + d];
#pragma unroll
            for (int j = 0; j < 8; j++) kf[j] = Ks[(c2 + 16 * j) * SSTR + d];
#pragma unroll
            for (int i = 0; i < 4; i++)
#pragma unroll
                for (int j = 0; j < 8; j++)
                    s[i][j] = fmaf(qf[i], kf[j], s[i][j]);
        }

        // ---- online softmax per row group (16 lanes share rows) ----
        float alpha[4];
#pragma unroll
        for (int i = 0; i < 4; i++) {
            float mt = s[i][0];
#pragma unroll
            for (int j = 1; j < 8; j++) mt = fmaxf(mt, s[i][j]);
            mt = fmaxf(mt, __shfl_xor_sync(0xffffffffu, mt, 1));
            mt = fmaxf(mt, __shfl_xor_sync(0xffffffffu, mt, 2));
            mt = fmaxf(mt, __shfl_xor_sync(0xffffffffu, mt, 4));
            mt = fmaxf(mt, __shfl_xor_sync(0xffffffffu, mt, 8));
            float mnew = fmaxf(m_run[i], mt);
            alpha[i] = __expf(m_run[i] - mnew);
            float ls = 0.f;
#pragma unroll
            for (int j = 0; j < 8; j++) {
                s[i][j] = __expf(s[i][j] - mnew);
                ls += s[i][j];
            }
            ls += __shfl_xor_sync(0xffffffffu, ls, 1);
            ls += __shfl_xor_sync(0xffffffffu, ls, 2);
            ls += __shfl_xor_sync(0xffffffffu, ls, 4);
            ls += __shfl_xor_sync(0xffffffffu, ls, 8);
            l_run[i] = l_run[i] * alpha[i] + ls;
            m_run[i] = mnew;
        }
        // write P (rows stride 2*SSTR: 128 cols + pad) and alpha
#pragma unroll
        for (int i = 0; i < 4; i++) {
            float* prow = Ps + (r2 + 16 * i) * (2 * SSTR);
#pragma unroll
            for (int j = 0; j < 8; j++) prow[c2 + 16 * j] = s[i][j];
            if (c2 == 0) alpha_s[r2 + 16 * i] = alpha[i];
        }
        __syncthreads();

        // ---- O = O*alpha + P @ V : 4 rows x 4 cols per thread ----
        float al[4];
#pragma unroll
        for (int i = 0; i < 4; i++) al[i] = alpha_s[ro + 16 * i];
#pragma unroll
        for (int i = 0; i < 4; i++)
#pragma unroll
            for (int j = 0; j < 4; j++) acc[i][j] *= al[i];
#pragma unroll 4
        for (int k = 0; k < TK; k++) {
            float pf[4], vf[4];
#pragma unroll
            for (int i = 0; i < 4; i++) pf[i] = Ps[(ro + 16 * i) * (2 * SSTR) + k];
#pragma unroll
            for (int j = 0; j < 4; j++) vf[j] = Vs[k * SSTR + co + 16 * j];
#pragma unroll
            for (int i = 0; i < 4; i++)
#pragma unroll
                for (int j = 0; j < 4; j++)
                    acc[i][j] = fmaf(pf[i], vf[j], acc[i][j]);
        }
    }

    // publish l, normalize, write out
    __syncthreads();
#pragma unroll
    for (int i = 0; i < 4; i++)
        if (c2 == 0) l_s[r2 + 16 * i] = l_run[i];
    __syncthreads();
#pragma unroll
    for (int i = 0; i < 4; i++) {
        float inv = 1.0f / l_s[ro + 16 * i];
        float* op = g_attn + (size_t)(qbase + ro + 16 * i) * D_ + hoff;
#pragma unroll
        for (int j = 0; j < 4; j++)
            op[co + 16 * j] = acc[i][j] * inv;
    }
}

// Smem: Qs 64*65 + Ks 128*65 + Vs 128*65 + Ps 64*130 + 128 = 33088 floats
#define ATTN_SMEM ((TQ * SSTR + 2 * TK * SSTR + TQ * 2 * SSTR + 2 * TQ) * (int)sizeof(float))

// ---------------------------------------------------------------------------
extern "C" void kernel_launch(void* const* d_in, const int* in_sizes, int n_in,
                              void* d_out, int out_size) {
    const float* utt = (const float*)d_in[0];
    const float* rc  = (const float*)d_in[1];
    const float* mem = (const float*)d_in[2];
    const float* lck = (const float*)d_in[3];
    const float* lcv = (const float*)d_in[4];
    const float* Wq  = (const float*)d_in[5];
    const float* bq  = (const float*)d_in[6];
    const float* Wkv = (const float*)d_in[7];
    const float* bkv = (const float*)d_in[8];
    const float* Wo  = (const float*)d_in[9];
    const float* bo  = (const float*)d_in[10];

    float* outBuf = (float*)d_out;                       // [2304,1024]
    float* keyBuf = outBuf + (size_t)QL * D_;            // [3840,1024]
    float* valBuf = keyBuf + (size_t)KVL * D_;           // [3840,1024]

    cudaFuncSetAttribute(attn_kernel, cudaFuncAttributeMaxDynamicSharedMemorySize,
                         ATTN_SMEM);

    gemm_q_kernel<<<dim3(QL / 64, D_ / 64), 256>>>(rc, utt, Wq, bq);
    gemm_kv_kernel<<<dim3((M_ + R_ + U_) / 64, 2 * D_ / 64), 256>>>(
        mem, rc, utt, Wkv, bkv, keyBuf, valBuf);
    cudaMemcpyAsync(keyBuf + (size_t)(M_ + R_) * D_, lck,
                    (size_t)L_ * D_ * sizeof(float), cudaMemcpyDeviceToDevice);
    cudaMemcpyAsync(valBuf + (size_t)(M_ + R_) * D_, lcv,
                    (size_t)L_ * D_ * sizeof(float), cudaMemcpyDeviceToDevice);
    attn_kernel<<<dim3(QL / TQ, NH), 256, ATTN_SMEM>>>(keyBuf, valBuf);
    gemm_o_kernel<<<dim3(QL / 64, D_ / 64), 256>>>(Wo, bo, outBuf);
}

// round 6
// speedup vs baseline: 3.8180x; 1.2265x over previous
#include <cuda_runtime.h>
#include <cuda_bf16.h>
#include <math.h>

#define D_   1024
#define U_   2048
#define R_   256
#define L_   1024
#define M_   512
#define QL   2304   // U + R
#define KVL  3840   // M + R + L + U
#define NH   16
#define HD   64

#define TQ   64     // q rows per attention block
#define TK   128    // kv rows per tile
#define QSTR 66     // Q/K smem stride (even -> 8B-aligned u64 loads, conflict-free)
#define VSTR 68     // V smem stride (mult of 4 -> 16B-aligned float4/ull2 loads)

typedef unsigned long long u64t;

__device__ __forceinline__ u64t pk2(float lo, float hi) {
    u64t r; asm("mov.b64 %0, {%1, %2};" : "=l"(r) : "f"(lo), "f"(hi)); return r;
}
__device__ __forceinline__ void upk2(u64t v, float& lo, float& hi) {
    asm("mov.b64 {%0, %1}, %2;" : "=f"(lo), "=f"(hi) : "l"(v));
}
__device__ __forceinline__ u64t f2fma(u64t a, u64t b, u64t c) {
    u64t d; asm("fma.rn.f32x2 %0, %1, %2, %3;" : "=l"(d) : "l"(a), "l"(b), "l"(c));
    return d;
}
__device__ __forceinline__ u64t f2mul(u64t a, u64t b) {
    u64t d; asm("mul.rn.f32x2 %0, %1, %2;" : "=l"(d) : "l"(a), "l"(b));
    return d;
}

// Scratch
__device__ float g_query[(size_t)QL * D_];
__device__ float g_attn[(size_t)QL * D_];

// ---------------------------------------------------------------------------
// 128x128 SGEMM tile, BK=16, 256 threads, 8x8 microtile, f32x2 FMA.
// A,B both row-major with K contiguous (C = A @ B^T). Smem stored [k][row].
// ---------------------------------------------------------------------------
#define GM 128
#define GK 16

__device__ __forceinline__ void gemm128_loop(const float* __restrict__ arow,
                                             const float* __restrict__ brow,
                                             float* As, float* Bs,
                                             int tid, u64t acc2[8][4]) {
    const int kseg = (tid >> 7) * 8;   // 0 or 8
    const int srow = tid & 127;
    const int m0 = (tid & 15) * 8;
    const int n0 = (tid >> 4) * 8;
    for (int kt = 0; kt < D_; kt += GK) {
        float4 a0 = *(const float4*)(arow + kt + kseg);
        float4 a1 = *(const float4*)(arow + kt + kseg + 4);
        float4 b0 = *(const float4*)(brow + kt + kseg);
        float4 b1 = *(const float4*)(brow + kt + kseg + 4);
        __syncthreads();
        As[(kseg + 0) * GM + srow] = a0.x; As[(kseg + 1) * GM + srow] = a0.y;
        As[(kseg + 2) * GM + srow] = a0.z; As[(kseg + 3) * GM + srow] = a0.w;
        As[(kseg + 4) * GM + srow] = a1.x; As[(kseg + 5) * GM + srow] = a1.y;
        As[(kseg + 6) * GM + srow] = a1.z; As[(kseg + 7) * GM + srow] = a1.w;
        Bs[(kseg + 0) * GM + srow] = b0.x; Bs[(kseg + 1) * GM + srow] = b0.y;
        Bs[(kseg + 2) * GM + srow] = b0.z; Bs[(kseg + 3) * GM + srow] = b0.w;
        Bs[(kseg + 4) * GM + srow] = b1.x; Bs[(kseg + 5) * GM + srow] = b1.y;
        Bs[(kseg + 6) * GM + srow] = b1.z; Bs[(kseg + 7) * GM + srow] = b1.w;
        __syncthreads();
#pragma unroll
        for (int k = 0; k < GK; k++) {
            const float* ar = As + k * GM + m0;
            float4 a4a = *(const float4*)ar;
            float4 a4b = *(const float4*)(ar + 4);
            const u64t* br = (const u64t*)(Bs + k * GM + n0);
            u64t b2[4] = {br[0], br[1], br[2], br[3]};
            float av[8] = {a4a.x, a4a.y, a4a.z, a4a.w, a4b.x, a4b.y, a4b.z, a4b.w};
#pragma unroll
            for (int i = 0; i < 8; i++) {
                u64t ai = pk2(av[i], av[i]);
#pragma unroll
                for (int jp = 0; jp < 4; jp++)
                    acc2[i][jp] = f2fma(ai, b2[jp], acc2[i][jp]);
            }
        }
    }
}

// query = concat(rc, utt) @ Wq^T + bq -> g_query
__global__ __launch_bounds__(256, 2) void gemm_q_kernel(const float* __restrict__ rc,
                                                        const float* __restrict__ utt,
                                                        const float* __restrict__ W,
                                                        const float* __restrict__ bias) {
    __shared__ __align__(16) float As[GK * GM];
    __shared__ __align__(16) float Bs[GK * GM];
    const int tid = threadIdx.x;
    const int bm = blockIdx.x * 128, bn = blockIdx.y * 128;
    const int arowi = bm + (tid & 127);
    const float* arow = (arowi < R_) ? rc + (size_t)arowi * D_
                                     : utt + (size_t)(arowi - R_) * D_;
    const float* brow = W + (size_t)(bn + (tid & 127)) * D_;
    u64t acc2[8][4];
#pragma unroll
    for (int i = 0; i < 8; i++)
#pragma unroll
        for (int j = 0; j < 4; j++) acc2[i][j] = 0ull;
    gemm128_loop(arow, brow, As, Bs, tid, acc2);
    const int m0 = (tid & 15) * 8, n0 = (tid >> 4) * 8;
    float4 bb0 = *(const float4*)(bias + bn + n0);
    float4 bb1 = *(const float4*)(bias + bn + n0 + 4);
#pragma unroll
    for (int i = 0; i < 8; i++) {
        float c[8];
        upk2(acc2[i][0], c[0], c[1]); upk2(acc2[i][1], c[2], c[3]);
        upk2(acc2[i][2], c[4], c[5]); upk2(acc2[i][3], c[6], c[7]);
        float* orow = g_query + (size_t)(bm + m0 + i) * D_ + bn + n0;
        *(float4*)orow = make_float4(c[0] + bb0.x, c[1] + bb0.y, c[2] + bb0.z, c[3] + bb0.w);
        *(float4*)(orow + 4) = make_float4(c[4] + bb1.x, c[5] + bb1.y, c[6] + bb1.z, c[7] + bb1.w);
    }
}

// kv = concat(mem, rc, utt) @ Wkv^T + bkv -> scattered into key/value buffers
__global__ __launch_bounds__(256, 2) void gemm_kv_kernel(const float* __restrict__ mem,
                                                         const float* __restrict__ rc,
                                                         const float* __restrict__ utt,
                                                         const float* __restrict__ W,
                                                         const float* __restrict__ bias,
                                                         float* __restrict__ keyBuf,
                                                         float* __restrict__ valBuf) {
    __shared__ __align__(16) float As[GK * GM];
    __shared__ __align__(16) float Bs[GK * GM];
    const int tid = threadIdx.x;
    const int bm = blockIdx.x * 128, bn = blockIdx.y * 128;
    const int arowi = bm + (tid & 127);
    const float* arow = (arowi < M_)      ? mem + (size_t)arowi * D_
                      : (arowi < M_ + R_) ? rc + (size_t)(arowi - M_) * D_
                                          : utt + (size_t)(arowi - M_ - R_) * D_;
    const float* brow = W + (size_t)(bn + (tid & 127)) * D_;
    u64t acc2[8][4];
#pragma unroll
    for (int i = 0; i < 8; i++)
#pragma unroll
        for (int j = 0; j < 4; j++) acc2[i][j] = 0ull;
    gemm128_loop(arow, brow, As, Bs, tid, acc2);
    const int m0 = (tid & 15) * 8, n0 = (tid >> 4) * 8;
    float4 bb0 = *(const float4*)(bias + bn + n0);
    float4 bb1 = *(const float4*)(bias + bn + n0 + 4);
    float* obase = (bn < D_) ? keyBuf : valBuf;
    const int ncol = (bn < D_) ? (bn + n0) : (bn - D_ + n0);
#pragma unroll
    for (int i = 0; i < 8; i++) {
        float c[8];
        upk2(acc2[i][0], c[0], c[1]); upk2(acc2[i][1], c[2], c[3]);
        upk2(acc2[i][2], c[4], c[5]); upk2(acc2[i][3], c[6], c[7]);
        int row = bm + m0 + i;
        int ro = (row < M_ + R_) ? row : row + L_;  // left-context gap at 768
        float* orow = obase + (size_t)ro * D_ + ncol;
        *(float4*)orow = make_float4(c[0] + bb0.x, c[1] + bb0.y, c[2] + bb0.z, c[3] + bb0.w);
        *(float4*)(orow + 4) = make_float4(c[4] + bb1.x, c[5] + bb1.y, c[6] + bb1.z, c[7] + bb1.w);
    }
}

// out = g_attn @ Wo^T + bo
__global__ __launch_bounds__(256, 2) void gemm_o_kernel(const float* __restrict__ W,
                                                        const float* __restrict__ bias,
                                                        float* __restrict__ outBuf) {
    __shared__ __align__(16) float As[GK * GM];
    __shared__ __align__(16) float Bs[GK * GM];
    const int tid = threadIdx.x;
    const int bm = blockIdx.x * 128, bn = blockIdx.y * 128;
    const float* arow = g_attn + (size_t)(bm + (tid & 127)) * D_;
    const float* brow = W + (size_t)(bn + (tid & 127)) * D_;
    u64t acc2[8][4];
#pragma unroll
    for (int i = 0; i < 8; i++)
#pragma unroll
        for (int j = 0; j < 4; j++) acc2[i][j] = 0ull;
    gemm128_loop(arow, brow, As, Bs, tid, acc2);
    const int m0 = (tid & 15) * 8, n0 = (tid >> 4) * 8;
    float4 bb0 = *(const float4*)(bias + bn + n0);
    float4 bb1 = *(const float4*)(bias + bn + n0 + 4);
#pragma unroll
    for (int i = 0; i < 8; i++) {
        float c[8];
        upk2(acc2[i][0], c[0], c[1]); upk2(acc2[i][1], c[2], c[3]);
        upk2(acc2[i][2], c[4], c[5]); upk2(acc2[i][3], c[6], c[7]);
        float* orow = outBuf + (size_t)(bm + m0 + i) * D_ + bn + n0;
        *(float4*)orow = make_float4(c[0] + bb0.x, c[1] + bb0.y, c[2] + bb0.z, c[3] + bb0.w);
        *(float4*)(orow + 4) = make_float4(c[4] + bb1.x, c[5] + bb1.y, c[6] + bb1.z, c[7] + bb1.w);
    }
}

// ---------------------------------------------------------------------------
// Flash attention v3 (f32x2): block = 64 q-rows x head, 256 threads, kv 128.
// S-phase: 4x8 micro, packed over d-pairs. P^T stored into the K buffer.
// O-phase: 1 row x 16 cols per thread, packed over col-pairs, V broadcast.
// Smem 86 KB -> 2 CTAs/SM.
// ---------------------------------------------------------------------------
__global__ __launch_bounds__(256, 2) void attn_kernel(const float* __restrict__ Kg,
                                                      const float* __restrict__ Vg) {
    extern __shared__ __align__(16) float sm[];
    float* Qs = sm;                         // [64][66]
    float* Ks = Qs + TQ * QSTR;             // [128][66]; becomes P^T[kv][q]
    float* Vs = Ks + TK * QSTR;             // [128][68]
    float* alpha_s = Vs + TK * VSTR;        // [64]
    float* l_s = alpha_s + TQ;              // [64]

    const int tid = threadIdx.x;
    const int qbase = blockIdx.x * TQ;
    const int hoff = blockIdx.y * HD;
    // S-phase mapping
    const int c2 = tid & 15;   // kv cols c2+16j, j<8
    const int r2 = tid >> 4;   // q rows r2+16i, i<4
    // O-phase mapping
    const int ro = tid & 63;   // q row
    const int cg = tid >> 6;   // dims 16*cg .. 16*cg+15

    // Load Q (pre-scaled by 1/8)
#pragma unroll
    for (int jj = 0; jj < 4; jj++) {
        int id = jj * 256 + tid;
        int row = id >> 4;
        int seg = (id & 15) * 4;
        float4 v = *(const float4*)(g_query + (size_t)(qbase + row) * D_ + hoff + seg);
        *(u64t*)(Qs + row * QSTR + seg)     = pk2(v.x * 0.125f, v.y * 0.125f);
        *(u64t*)(Qs + row * QSTR + seg + 2) = pk2(v.z * 0.125f, v.w * 0.125f);
    }

    u64t oacc[8];
#pragma unroll
    for (int j = 0; j < 8; j++) oacc[j] = 0ull;
    float m_run[4], l_run[4];
#pragma unroll
    for (int i = 0; i < 4; i++) { m_run[i] = -INFINITY; l_run[i] = 0.f; }

    for (int kt = 0; kt < KVL; kt += TK) {
        __syncthreads();  // prev O-phase done with Vs / P^T(Ks)
#pragma unroll
        for (int jj = 0; jj < 8; jj++) {
            int id = jj * 256 + tid;
            int row = id >> 4;
            int seg = (id & 15) * 4;
            float4 k4 = *(const float4*)(Kg + (size_t)(kt + row) * D_ + hoff + seg);
            *(u64t*)(Ks + row * QSTR + seg)     = pk2(k4.x, k4.y);
            *(u64t*)(Ks + row * QSTR + seg + 2) = pk2(k4.z, k4.w);
            float4 v4 = *(const float4*)(Vg + (size_t)(kt + row) * D_ + hoff + seg);
            *(float4*)(Vs + row * VSTR + seg) = v4;
        }
        __syncthreads();

        // ---- S = Q @ K^T, packed over d pairs ----
        u64t s2[4][8];
#pragma unroll
        for (int i = 0; i < 4; i++)
#pragma unroll
            for (int j = 0; j < 8; j++) s2[i][j] = 0ull;
#pragma unroll 4
        for (int d = 0; d < HD; d += 2) {
            u64t q2[4], k2[8];
#pragma unroll
            for (int i = 0; i < 4; i++)
                q2[i] = *(const u64t*)(Qs + (r2 + 16 * i) * QSTR + d);
#pragma unroll
            for (int j = 0; j < 8; j++)
                k2[j] = *(const u64t*)(Ks + (c2 + 16 * j) * QSTR + d);
#pragma unroll
            for (int i = 0; i < 4; i++)
#pragma unroll
                for (int j = 0; j < 8; j++)
                    s2[i][j] = f2fma(q2[i], k2[j], s2[i][j]);
        }
        float s[4][8];
#pragma unroll
        for (int i = 0; i < 4; i++)
#pragma unroll
            for (int j = 0; j < 8; j++) {
                float lo, hi; upk2(s2[i][j], lo, hi);
                s[i][j] = lo + hi;
            }

        // ---- online softmax per row group ----
        float alpha[4];
#pragma unroll
        for (int i = 0; i < 4; i++) {
            float mt = s[i][0];
#pragma unroll
            for (int j = 1; j < 8; j++) mt = fmaxf(mt, s[i][j]);
            mt = fmaxf(mt, __shfl_xor_sync(0xffffffffu, mt, 1));
            mt = fmaxf(mt, __shfl_xor_sync(0xffffffffu, mt, 2));
            mt = fmaxf(mt, __shfl_xor_sync(0xffffffffu, mt, 4));
            mt = fmaxf(mt, __shfl_xor_sync(0xffffffffu, mt, 8));
            float mnew = fmaxf(m_run[i], mt);
            alpha[i] = __expf(m_run[i] - mnew);
            float ls = 0.f;
#pragma unroll
            for (int j = 0; j < 8; j++) { s[i][j] = __expf(s[i][j] - mnew); ls += s[i][j]; }
            ls += __shfl_xor_sync(0xffffffffu, ls, 1);
            ls += __shfl_xor_sync(0xffffffffu, ls, 2);
            ls += __shfl_xor_sync(0xffffffffu, ls, 4);
            ls += __shfl_xor_sync(0xffffffffu, ls, 8);
            l_run[i] = l_run[i] * alpha[i] + ls;
            m_run[i] = mnew;
        }

        __syncthreads();  // all S reads of Ks complete before P^T overwrite
#pragma unroll
        for (int i = 0; i < 4; i++) {
#pragma unroll
            for (int j = 0; j < 8; j++)
                Ks[(c2 + 16 * j) * QSTR + (r2 + 16 * i)] = s[i][j];  // P^T[kv][q]
            if (c2 == 0) alpha_s[r2 + 16 * i] = alpha[i];
        }
        __syncthreads();

        // ---- O = O*alpha + P @ V ----
        {
            float al = alpha_s[ro];
            u64t al2 = pk2(al, al);
#pragma unroll
            for (int j = 0; j < 8; j++) oacc[j] = f2mul(oacc[j], al2);
        }
#pragma unroll 4
        for (int k = 0; k < TK; k++) {
            float p = Ks[k * QSTR + ro];
            u64t p2 = pk2(p, p);
            const ulonglong2* vr = (const ulonglong2*)(Vs + k * VSTR + 16 * cg);
            ulonglong2 va = vr[0], vb = vr[1];
            oacc[0] = f2fma(p2, va.x, oacc[0]);
            oacc[1] = f2fma(p2, va.y, oacc[1]);
            oacc[2] = f2fma(p2, vb.x, oacc[2]);
            oacc[3] = f2fma(p2, vb.y, oacc[3]);
            ulonglong2 vc = vr[2], vd = vr[3];
            oacc[4] = f2fma(p2, vc.x, oacc[4]);
            oacc[5] = f2fma(p2, vc.y, oacc[5]);
            oacc[6] = f2fma(p2, vd.x, oacc[6]);
            oacc[7] = f2fma(p2, vd.y, oacc[7]);
        }
    }

    __syncthreads();
#pragma unroll
    for (int i = 0; i < 4; i++)
        if (c2 == 0) l_s[r2 + 16 * i] = l_run[i];
    __syncthreads();
    {
        float inv = 1.0f / l_s[ro];
        u64t inv2 = pk2(inv, inv);
        float* op = g_attn + (size_t)(qbase + ro) * D_ + hoff + 16 * cg;
#pragma unroll
        for (int q = 0; q < 4; q++) {
            float4 o4;
            u64t lo64 = f2mul(oacc[2 * q], inv2);
            u64t hi64 = f2mul(oacc[2 * q + 1], inv2);
            upk2(lo64, o4.x, o4.y);
            upk2(hi64, o4.z, o4.w);
            *(float4*)(op + 4 * q) = o4;
        }
    }
}

#define ATTN_SMEM ((TQ * QSTR + TK * QSTR + TK * VSTR + 2 * TQ) * (int)sizeof(float))

// ---------------------------------------------------------------------------
extern "C" void kernel_launch(void* const* d_in, const int* in_sizes, int n_in,
                              void* d_out, int out_size) {
    const float* utt = (const float*)d_in[0];
    const float* rc  = (const float*)d_in[1];
    const float* mem = (const float*)d_in[2];
    const float* lck = (const float*)d_in[3];
    const float* lcv = (const float*)d_in[4];
    const float* Wq  = (const float*)d_in[5];
    const float* bq  = (const float*)d_in[6];
    const float* Wkv = (const float*)d_in[7];
    const float* bkv = (const float*)d_in[8];
    const float* Wo  = (const float*)d_in[9];
    const float* bo  = (const float*)d_in[10];

    float* outBuf = (float*)d_out;                       // [2304,1024]
    float* keyBuf = outBuf + (size_t)QL * D_;            // [3840,1024]
    float* valBuf = keyBuf + (size_t)KVL * D_;           // [3840,1024]

    cudaFuncSetAttribute(attn_kernel, cudaFuncAttributeMaxDynamicSharedMemorySize,
                         ATTN_SMEM);

    gemm_q_kernel<<<dim3(QL / 128, D_ / 128), 256>>>(rc, utt, Wq, bq);
    gemm_kv_kernel<<<dim3((M_ + R_ + U_) / 128, 2 * D_ / 128), 256>>>(
        mem, rc, utt, Wkv, bkv, keyBuf, valBuf);
    cudaMemcpyAsync(keyBuf + (size_t)(M_ + R_) * D_, lck,
                    (size_t)L_ * D_ * sizeof(float), cudaMemcpyDeviceToDevice);
    cudaMemcpyAsync(valBuf + (size_t)(M_ + R_) * D_, lcv,
                    (size_t)L_ * D_ * sizeof(float), cudaMemcpyDeviceToDevice);
    attn_kernel<<<dim3(QL / TQ, NH), 256, ATTN_SMEM>>>(keyBuf, valBuf);
    gemm_o_kernel<<<dim3(QL / 128, D_ / 128), 256>>>(Wo, bo, outBuf);
}

// round 7
// speedup vs baseline: 4.9956x; 1.3084x over previous
#include <cuda_runtime.h>
#include <cuda_bf16.h>
#include <math.h>

#define D_   1024
#define U_   2048
#define R_   256
#define L_   1024
#define M_   512
#define QL   2304   // U + R
#define KVL  3840   // M + R + L + U
#define NH   16
#define HD   64

#define TQ   64     // q rows per attention block
#define TK   128    // kv rows per tile
#define QSTR 66     // Q/K smem stride (even -> 8B-aligned u64 loads, conflict-free)
#define VSTR 68     // V smem stride (mult of 4 -> 16B-aligned float4/ull2 loads)

typedef unsigned long long u64t;

__device__ __forceinline__ u64t pk2(float lo, float hi) {
    u64t r; asm("mov.b64 %0, {%1, %2};" : "=l"(r) : "f"(lo), "f"(hi)); return r;
}
__device__ __forceinline__ void upk2(u64t v, float& lo, float& hi) {
    asm("mov.b64 {%0, %1}, %2;" : "=f"(lo), "=f"(hi) : "l"(v));
}
__device__ __forceinline__ u64t f2fma(u64t a, u64t b, u64t c) {
    u64t d; asm("fma.rn.f32x2 %0, %1, %2, %3;" : "=l"(d) : "l"(a), "l"(b), "l"(c));
    return d;
}
__device__ __forceinline__ u64t f2mul(u64t a, u64t b) {
    u64t d; asm("mul.rn.f32x2 %0, %1, %2;" : "=l"(d) : "l"(a), "l"(b));
    return d;
}

// Scratch
__device__ float g_query[(size_t)QL * D_];
__device__ float g_attn[(size_t)QL * D_];

// ===========================================================================
// tf32 tensor-core GEMM: C(128x128) = A @ B^T (+bias), both row-major K-contig
// 256 threads = 8 warps (2m x 4n), warp tile 64x32, mma.m16n8k8.tf32.
// ===========================================================================
#define BM 128
#define BK 32
#define KSTR 36   // smem stride in words: frag addr = 4*(lane>>2)+(lane&3) mod 32 -> conflict-free

__device__ __forceinline__ unsigned f2tf(float f) {
    unsigned r; asm("cvt.rna.tf32.f32 %0, %1;" : "=r"(r) : "f"(f)); return r;
}

__device__ __forceinline__ void mma_tf32(float c[4], unsigned a0, unsigned a1,
                                         unsigned a2, unsigned a3,
                                         unsigned b0, unsigned b1) {
    asm("mma.sync.aligned.m16n8k8.row.col.f32.tf32.tf32.f32 "
        "{%0,%1,%2,%3}, {%4,%5,%6,%7}, {%8,%9}, {%0,%1,%2,%3};"
        : "+f"(c[0]), "+f"(c[1]), "+f"(c[2]), "+f"(c[3])
        : "r"(a0), "r"(a1), "r"(a2), "r"(a3), "r"(b0), "r"(b1));
}

__device__ __forceinline__ void mma_gemm_loop(const float* __restrict__ arow,
                                              const float* __restrict__ brow,
                                              unsigned* As, unsigned* Bs, int tid,
                                              float c[4][4][4]) {
    const int lseg = (tid & 1) * 16;
    const int lrow = tid >> 1;
    const int lane = tid & 31;
    const int wid = tid >> 5;
    const int wm = (wid >> 2) * 64;
    const int wn = (wid & 3) * 32;
    const int gr = lane >> 2, tg = lane & 3;
    for (int kt = 0; kt < D_; kt += BK) {
        float4 a[4], b[4];
#pragma unroll
        for (int j = 0; j < 4; j++) {
            a[j] = *(const float4*)(arow + kt + lseg + 4 * j);
            b[j] = *(const float4*)(brow + kt + lseg + 4 * j);
        }
        __syncthreads();
#pragma unroll
        for (int j = 0; j < 4; j++) {
            *(uint4*)(As + lrow * KSTR + lseg + 4 * j) =
                make_uint4(f2tf(a[j].x), f2tf(a[j].y), f2tf(a[j].z), f2tf(a[j].w));
            *(uint4*)(Bs + lrow * KSTR + lseg + 4 * j) =
                make_uint4(f2tf(b[j].x), f2tf(b[j].y), f2tf(b[j].z), f2tf(b[j].w));
        }
        __syncthreads();
#pragma unroll
        for (int ks = 0; ks < 4; ks++) {
            unsigned af[4][4], bf[4][2];
#pragma unroll
            for (int mi = 0; mi < 4; mi++) {
                const unsigned* ab = As + (wm + mi * 16 + gr) * KSTR + ks * 8 + tg;
                af[mi][0] = ab[0];
                af[mi][1] = ab[8 * KSTR];
                af[mi][2] = ab[4];
                af[mi][3] = ab[8 * KSTR + 4];
            }
#pragma unroll
            for (int ni = 0; ni < 4; ni++) {
                const unsigned* bb = Bs + (wn + ni * 8 + gr) * KSTR + ks * 8 + tg;
                bf[ni][0] = bb[0];
                bf[ni][1] = bb[4];
            }
#pragma unroll
            for (int mi = 0; mi < 4; mi++)
#pragma unroll
                for (int ni = 0; ni < 4; ni++)
                    mma_tf32(c[mi][ni], af[mi][0], af[mi][1], af[mi][2], af[mi][3],
                             bf[ni][0], bf[ni][1]);
        }
    }
}

// Epilogue helper: per-thread fragment -> rows/cols with bias, float2 stores.
__device__ __forceinline__ void mma_epilogue(float c[4][4][4], int tid,
                                             const float* __restrict__ bias, int bn,
                                             float* __restrict__ out, int ldo,
                                             int bm, bool kvScatter) {
    const int lane = tid & 31;
    const int wid = tid >> 5;
    const int wm = (wid >> 2) * 64;
    const int wn = (wid & 3) * 32;
    const int gr = lane >> 2, tg = lane & 3;
#pragma unroll
    for (int ni = 0; ni < 4; ni++) {
        int col = wn + ni * 8 + tg * 2;  // relative to bn
        float2 bb = *(const float2*)(bias + bn + col);
#pragma unroll
        for (int mi = 0; mi < 4; mi++) {
#pragma unroll
            for (int h = 0; h < 2; h++) {
                int row = bm + wm + mi * 16 + gr + h * 8;
                if (kvScatter && row >= M_ + R_) row += L_;  // left-context gap
                *(float2*)(out + (size_t)row * ldo + (col & 127) + (bn & 127) * 0) = // placeholder
                    make_float2(0.f, 0.f);
            }
        }
    }
}

// query = concat(rc, utt) @ Wq^T + bq -> g_query
__global__ __launch_bounds__(256) void gemm_q_kernel(const float* __restrict__ rc,
                                                     const float* __restrict__ utt,
                                                     const float* __restrict__ W,
                                                     const float* __restrict__ bias) {
    __shared__ __align__(16) unsigned As[BM * KSTR];
    __shared__ __align__(16) unsigned Bs[BM * KSTR];
    const int tid = threadIdx.x;
    const int bm = blockIdx.x * BM, bn = blockIdx.y * BM;
    const int arowi = bm + (tid >> 1);
    const float* arow = (arowi < R_) ? rc + (size_t)arowi * D_
                                     : utt + (size_t)(arowi - R_) * D_;
    const float* brow = W + (size_t)(bn + (tid >> 1)) * D_;
    float c[4][4][4];
#pragma unroll
    for (int a = 0; a < 4; a++)
#pragma unroll
        for (int b = 0; b < 4; b++)
#pragma unroll
            for (int d = 0; d < 4; d++) c[a][b][d] = 0.f;
    mma_gemm_loop(arow, brow, As, Bs, tid, c);
    const int lane = tid & 31;
    const int wid = tid >> 5;
    const int wm = (wid >> 2) * 64, wn = (wid & 3) * 32;
    const int gr = lane >> 2, tg = lane & 3;
#pragma unroll
    for (int ni = 0; ni < 4; ni++) {
        int col = bn + wn + ni * 8 + tg * 2;
        float2 bb = *(const float2*)(bias + col);
#pragma unroll
        for (int mi = 0; mi < 4; mi++) {
            int row = bm + wm + mi * 16 + gr;
            *(float2*)(g_query + (size_t)row * D_ + col) =
                make_float2(c[mi][ni][0] + bb.x, c[mi][ni][1] + bb.y);
            *(float2*)(g_query + (size_t)(row + 8) * D_ + col) =
                make_float2(c[mi][ni][2] + bb.x, c[mi][ni][3] + bb.y);
        }
    }
}

// kv = concat(mem, rc, utt) @ Wkv^T + bkv -> scattered into key/value buffers
__global__ __launch_bounds__(256) void gemm_kv_kernel(const float* __restrict__ mem,
                                                      const float* __restrict__ rc,
                                                      const float* __restrict__ utt,
                                                      const float* __restrict__ W,
                                                      const float* __restrict__ bias,
                                                      float* __restrict__ keyBuf,
                                                      float* __restrict__ valBuf) {
    __shared__ __align__(16) unsigned As[BM * KSTR];
    __shared__ __align__(16) unsigned Bs[BM * KSTR];
    const int tid = threadIdx.x;
    const int bm = blockIdx.x * BM, bn = blockIdx.y * BM;
    const int arowi = bm + (tid >> 1);
    const float* arow = (arowi < M_)      ? mem + (size_t)arowi * D_
                      : (arowi < M_ + R_) ? rc + (size_t)(arowi - M_) * D_
                                          : utt + (size_t)(arowi - M_ - R_) * D_;
    const float* brow = W + (size_t)(bn + (tid >> 1)) * D_;
    float c[4][4][4];
#pragma unroll
    for (int a = 0; a < 4; a++)
#pragma unroll
        for (int b = 0; b < 4; b++)
#pragma unroll
            for (int d = 0; d < 4; d++) c[a][b][d] = 0.f;
    mma_gemm_loop(arow, brow, As, Bs, tid, c);
    const int lane = tid & 31;
    const int wid = tid >> 5;
    const int wm = (wid >> 2) * 64, wn = (wid & 3) * 32;
    const int gr = lane >> 2, tg = lane & 3;
    float* obase = (bn < D_) ? keyBuf : valBuf;
    const int cb = (bn < D_) ? bn : bn - D_;
#pragma unroll
    for (int ni = 0; ni < 4; ni++) {
        int col = cb + wn + ni * 8 + tg * 2;
        float2 bb = *(const float2*)(bias + bn + wn + ni * 8 + tg * 2);
#pragma unroll
        for (int mi = 0; mi < 4; mi++) {
            int row0 = bm + wm + mi * 16 + gr;
            int ro0 = (row0 < M_ + R_) ? row0 : row0 + L_;
            int row1 = row0 + 8;
            int ro1 = (row1 < M_ + R_) ? row1 : row1 + L_;
            *(float2*)(obase + (size_t)ro0 * D_ + col) =
                make_float2(c[mi][ni][0] + bb.x, c[mi][ni][1] + bb.y);
            *(float2*)(obase + (size_t)ro1 * D_ + col) =
                make_float2(c[mi][ni][2] + bb.x, c[mi][ni][3] + bb.y);
        }
    }
}

// out = g_attn @ Wo^T + bo
__global__ __launch_bounds__(256) void gemm_o_kernel(const float* __restrict__ W,
                                                     const float* __restrict__ bias,
                                                     float* __restrict__ outBuf) {
    __shared__ __align__(16) unsigned As[BM * KSTR];
    __shared__ __align__(16) unsigned Bs[BM * KSTR];
    const int tid = threadIdx.x;
    const int bm = blockIdx.x * BM, bn = blockIdx.y * BM;
    const float* arow = g_attn + (size_t)(bm + (tid >> 1)) * D_;
    const float* brow = W + (size_t)(bn + (tid >> 1)) * D_;
    float c[4][4][4];
#pragma unroll
    for (int a = 0; a < 4; a++)
#pragma unroll
        for (int b = 0; b < 4; b++)
#pragma unroll
            for (int d = 0; d < 4; d++) c[a][b][d] = 0.f;
    mma_gemm_loop(arow, brow, As, Bs, tid, c);
    const int lane = tid & 31;
    const int wid = tid >> 5;
    const int wm = (wid >> 2) * 64, wn = (wid & 3) * 32;
    const int gr = lane >> 2, tg = lane & 3;
#pragma unroll
    for (int ni = 0; ni < 4; ni++) {
        int col = bn + wn + ni * 8 + tg * 2;
        float2 bb = *(const float2*)(bias + col);
#pragma unroll
        for (int mi = 0; mi < 4; mi++) {
            int row = bm + wm + mi * 16 + gr;
            *(float2*)(outBuf + (size_t)row * D_ + col) =
                make_float2(c[mi][ni][0] + bb.x, c[mi][ni][1] + bb.y);
            *(float2*)(outBuf + (size_t)(row + 8) * D_ + col) =
                make_float2(c[mi][ni][2] + bb.x, c[mi][ni][3] + bb.y);
        }
    }
}

// ---------------------------------------------------------------------------
// Flash attention v3 (f32x2) — unchanged from round 6.
// ---------------------------------------------------------------------------
__global__ __launch_bounds__(256, 2) void attn_kernel(const float* __restrict__ Kg,
                                                      const float* __restrict__ Vg) {
    extern __shared__ __align__(16) float sm[];
    float* Qs = sm;                         // [64][66]
    float* Ks = Qs + TQ * QSTR;             // [128][66]; becomes P^T[kv][q]
    float* Vs = Ks + TK * QSTR;             // [128][68]
    float* alpha_s = Vs + TK * VSTR;        // [64]
    float* l_s = alpha_s + TQ;              // [64]

    const int tid = threadIdx.x;
    const int qbase = blockIdx.x * TQ;
    const int hoff = blockIdx.y * HD;
    const int c2 = tid & 15;
    const int r2 = tid >> 4;
    const int ro = tid & 63;
    const int cg = tid >> 6;

#pragma unroll
    for (int jj = 0; jj < 4; jj++) {
        int id = jj * 256 + tid;
        int row = id >> 4;
        int seg = (id & 15) * 4;
        float4 v = *(const float4*)(g_query + (size_t)(qbase + row) * D_ + hoff + seg);
        *(u64t*)(Qs + row * QSTR + seg)     = pk2(v.x * 0.125f, v.y * 0.125f);
        *(u64t*)(Qs + row * QSTR + seg + 2) = pk2(v.z * 0.125f, v.w * 0.125f);
    }

    u64t oacc[8];
#pragma unroll
    for (int j = 0; j < 8; j++) oacc[j] = 0ull;
    float m_run[4], l_run[4];
#pragma unroll
    for (int i = 0; i < 4; i++) { m_run[i] = -INFINITY; l_run[i] = 0.f; }

    for (int kt = 0; kt < KVL; kt += TK) {
        __syncthreads();
#pragma unroll
        for (int jj = 0; jj < 8; jj++) {
            int id = jj * 256 + tid;
            int row = id >> 4;
            int seg = (id & 15) * 4;
            float4 k4 = *(const float4*)(Kg + (size_t)(kt + row) * D_ + hoff + seg);
            *(u64t*)(Ks + row * QSTR + seg)     = pk2(k4.x, k4.y);
            *(u64t*)(Ks + row * QSTR + seg + 2) = pk2(k4.z, k4.w);
            float4 v4 = *(const float4*)(Vg + (size_t)(kt + row) * D_ + hoff + seg);
            *(float4*)(Vs + row * VSTR + seg) = v4;
        }
        __syncthreads();

        u64t s2[4][8];
#pragma unroll
        for (int i = 0; i < 4; i++)
#pragma unroll
            for (int j = 0; j < 8; j++) s2[i][j] = 0ull;
#pragma unroll 4
        for (int d = 0; d < HD; d += 2) {
            u64t q2[4], k2[8];
#pragma unroll
            for (int i = 0; i < 4; i++)
                q2[i] = *(const u64t*)(Qs + (r2 + 16 * i) * QSTR + d);
#pragma unroll
            for (int j = 0; j < 8; j++)
                k2[j] = *(const u64t*)(Ks + (c2 + 16 * j) * QSTR + d);
#pragma unroll
            for (int i = 0; i < 4; i++)
#pragma unroll
                for (int j = 0; j < 8; j++)
                    s2[i][j] = f2fma(q2[i], k2[j], s2[i][j]);
        }
        float s[4][8];
#pragma unroll
        for (int i = 0; i < 4; i++)
#pragma unroll
            for (int j = 0; j < 8; j++) {
                float lo, hi; upk2(s2[i][j], lo, hi);
                s[i][j] = lo + hi;
            }

        float alpha[4];
#pragma unroll
        for (int i = 0; i < 4; i++) {
            float mt = s[i][0];
#pragma unroll
            for (int j = 1; j < 8; j++) mt = fmaxf(mt, s[i][j]);
            mt = fmaxf(mt, __shfl_xor_sync(0xffffffffu, mt, 1));
            mt = fmaxf(mt, __shfl_xor_sync(0xffffffffu, mt, 2));
            mt = fmaxf(mt, __shfl_xor_sync(0xffffffffu, mt, 4));
            mt = fmaxf(mt, __shfl_xor_sync(0xffffffffu, mt, 8));
            float mnew = fmaxf(m_run[i], mt);
            alpha[i] = __expf(m_run[i] - mnew);
            float ls = 0.f;
#pragma unroll
            for (int j = 0; j < 8; j++) { s[i][j] = __expf(s[i][j] - mnew); ls += s[i][j]; }
            ls += __shfl_xor_sync(0xffffffffu, ls, 1);
            ls += __shfl_xor_sync(0xffffffffu, ls, 2);
            ls += __shfl_xor_sync(0xffffffffu, ls, 4);
            ls += __shfl_xor_sync(0xffffffffu, ls, 8);
            l_run[i] = l_run[i] * alpha[i] + ls;
            m_run[i] = mnew;
        }

        __syncthreads();
#pragma unroll
        for (int i = 0; i < 4; i++) {
#pragma unroll
            for (int j = 0; j < 8; j++)
                Ks[(c2 + 16 * j) * QSTR + (r2 + 16 * i)] = s[i][j];
            if (c2 == 0) alpha_s[r2 + 16 * i] = alpha[i];
        }
        __syncthreads();

        {
            float al = alpha_s[ro];
            u64t al2 = pk2(al, al);
#pragma unroll
            for (int j = 0; j < 8; j++) oacc[j] = f2mul(oacc[j], al2);
        }
#pragma unroll 4
        for (int k = 0; k < TK; k++) {
            float p = Ks[k * QSTR + ro];
            u64t p2 = pk2(p, p);
            const ulonglong2* vr = (const ulonglong2*)(Vs + k * VSTR + 16 * cg);
            ulonglong2 va = vr[0], vb = vr[1];
            oacc[0] = f2fma(p2, va.x, oacc[0]);
            oacc[1] = f2fma(p2, va.y, oacc[1]);
            oacc[2] = f2fma(p2, vb.x, oacc[2]);
            oacc[3] = f2fma(p2, vb.y, oacc[3]);
            ulonglong2 vc = vr[2], vd = vr[3];
            oacc[4] = f2fma(p2, vc.x, oacc[4]);
            oacc[5] = f2fma(p2, vc.y, oacc[5]);
            oacc[6] = f2fma(p2, vd.x, oacc[6]);
            oacc[7] = f2fma(p2, vd.y, oacc[7]);
        }
    }

    __syncthreads();
#pragma unroll
    for (int i = 0; i < 4; i++)
        if (c2 == 0) l_s[r2 + 16 * i] = l_run[i];
    __syncthreads();
    {
        float inv = 1.0f / l_s[ro];
        u64t inv2 = pk2(inv, inv);
        float* op = g_attn + (size_t)(qbase + ro) * D_ + hoff + 16 * cg;
#pragma unroll
        for (int q = 0; q < 4; q++) {
            float4 o4;
            u64t lo64 = f2mul(oacc[2 * q], inv2);
            u64t hi64 = f2mul(oacc[2 * q + 1], inv2);
            upk2(lo64, o4.x, o4.y);
            upk2(hi64, o4.z, o4.w);
            *(float4*)(op + 4 * q) = o4;
        }
    }
}

#define ATTN_SMEM ((TQ * QSTR + TK * QSTR + TK * VSTR + 2 * TQ) * (int)sizeof(float))

// ---------------------------------------------------------------------------
extern "C" void kernel_launch(void* const* d_in, const int* in_sizes, int n_in,
                              void* d_out, int out_size) {
    const float* utt = (const float*)d_in[0];
    const float* rc  = (const float*)d_in[1];
    const float* mem = (const float*)d_in[2];
    const float* lck = (const float*)d_in[3];
    const float* lcv = (const float*)d_in[4];
    const float* Wq  = (const float*)d_in[5];
    const float* bq  = (const float*)d_in[6];
    const float* Wkv = (const float*)d_in[7];
    const float* bkv = (const float*)d_in[8];
    const float* Wo  = (const float*)d_in[9];
    const float* bo  = (const float*)d_in[10];

    float* outBuf = (float*)d_out;                       // [2304,1024]
    float* keyBuf = outBuf + (size_t)QL * D_;            // [3840,1024]
    float* valBuf = keyBuf + (size_t)KVL * D_;           // [3840,1024]

    cudaFuncSetAttribute(attn_kernel, cudaFuncAttributeMaxDynamicSharedMemorySize,
                         ATTN_SMEM);

    gemm_q_kernel<<<dim3(QL / BM, D_ / BM), 256>>>(rc, utt, Wq, bq);
    gemm_kv_kernel<<<dim3((M_ + R_ + U_) / BM, 2 * D_ / BM), 256>>>(
        mem, rc, utt, Wkv, bkv, keyBuf, valBuf);
    cudaMemcpyAsync(keyBuf + (size_t)(M_ + R_) * D_, lck,
                    (size_t)L_ * D_ * sizeof(float), cudaMemcpyDeviceToDevice);
    cudaMemcpyAsync(valBuf + (size_t)(M_ + R_) * D_, lcv,
                    (size_t)L_ * D_ * sizeof(float), cudaMemcpyDeviceToDevice);
    attn_kernel<<<dim3(QL / TQ, NH), 256, ATTN_SMEM>>>(keyBuf, valBuf);
    gemm_o_kernel<<<dim3(QL / BM, D_ / BM), 256>>>(Wo, bo, outBuf);
}

// round 9
// speedup vs baseline: 7.4658x; 1.4945x over previous
#include <cuda_runtime.h>
#include <cuda_bf16.h>
#include <math.h>

#define D_   1024
#define U_   2048
#define R_   256
#define L_   1024
#define M_   512
#define QL   2304   // U + R
#define KVL  3840   // M + R + L + U
#define NH   16
#define HD   64

// Scratch
__device__ float g_query[(size_t)QL * D_];
__device__ float g_attn[(size_t)QL * D_];

// ===========================================================================
// tf32 tensor-core GEMM: C(128x128) = A @ B^T (+bias), both row-major K-contig
// 256 threads = 8 warps (2m x 4n), warp tile 64x32, mma.m16n8k8.tf32.
// ===========================================================================
#define BM 128
#define BK 32
#define KSTR 36   // smem stride words -> fragment LDS conflict-free

__device__ __forceinline__ unsigned f2tf(float f) {
    unsigned r; asm("cvt.rna.tf32.f32 %0, %1;" : "=r"(r) : "f"(f)); return r;
}

__device__ __forceinline__ void mma_tf32(float c[4], unsigned a0, unsigned a1,
                                         unsigned a2, unsigned a3,
                                         unsigned b0, unsigned b1) {
    asm("mma.sync.aligned.m16n8k8.row.col.f32.tf32.tf32.f32 "
        "{%0,%1,%2,%3}, {%4,%5,%6,%7}, {%8,%9}, {%0,%1,%2,%3};"
        : "+f"(c[0]), "+f"(c[1]), "+f"(c[2]), "+f"(c[3])
        : "r"(a0), "r"(a1), "r"(a2), "r"(a3), "r"(b0), "r"(b1));
}

__device__ __forceinline__ void mma_gemm_loop(const float* __restrict__ arow,
                                              const float* __restrict__ brow,
                                              unsigned* As, unsigned* Bs, int tid,
                                              float c[4][4][4]) {
    const int lseg = (tid & 1) * 16;
    const int lrow = tid >> 1;
    const int lane = tid & 31;
    const int wid = tid >> 5;
    const int wm = (wid >> 2) * 64;
    const int wn = (wid & 3) * 32;
    const int gr = lane >> 2, tg = lane & 3;
    for (int kt = 0; kt < D_; kt += BK) {
        float4 a[4], b[4];
#pragma unroll
        for (int j = 0; j < 4; j++) {
            a[j] = *(const float4*)(arow + kt + lseg + 4 * j);
            b[j] = *(const float4*)(brow + kt + lseg + 4 * j);
        }
        __syncthreads();
#pragma unroll
        for (int j = 0; j < 4; j++) {
            *(uint4*)(As + lrow * KSTR + lseg + 4 * j) =
                make_uint4(f2tf(a[j].x), f2tf(a[j].y), f2tf(a[j].z), f2tf(a[j].w));
            *(uint4*)(Bs + lrow * KSTR + lseg + 4 * j) =
                make_uint4(f2tf(b[j].x), f2tf(b[j].y), f2tf(b[j].z), f2tf(b[j].w));
        }
        __syncthreads();
#pragma unroll
        for (int ks = 0; ks < 4; ks++) {
            unsigned af[4][4], bf[4][2];
#pragma unroll
            for (int mi = 0; mi < 4; mi++) {
                const unsigned* ab = As + (wm + mi * 16 + gr) * KSTR + ks * 8 + tg;
                af[mi][0] = ab[0];
                af[mi][1] = ab[8 * KSTR];
                af[mi][2] = ab[4];
                af[mi][3] = ab[8 * KSTR + 4];
            }
#pragma unroll
            for (int ni = 0; ni < 4; ni++) {
                const unsigned* bb = Bs + (wn + ni * 8 + gr) * KSTR + ks * 8 + tg;
                bf[ni][0] = bb[0];
                bf[ni][1] = bb[4];
            }
#pragma unroll
            for (int mi = 0; mi < 4; mi++)
#pragma unroll
                for (int ni = 0; ni < 4; ni++)
                    mma_tf32(c[mi][ni], af[mi][0], af[mi][1], af[mi][2], af[mi][3],
                             bf[ni][0], bf[ni][1]);
        }
    }
}

// query = concat(rc, utt) @ Wq^T + bq -> g_query
__global__ __launch_bounds__(256) void gemm_q_kernel(const float* __restrict__ rc,
                                                     const float* __restrict__ utt,
                                                     const float* __restrict__ W,
                                                     const float* __restrict__ bias) {
    __shared__ __align__(16) unsigned As[BM * KSTR];
    __shared__ __align__(16) unsigned Bs[BM * KSTR];
    const int tid = threadIdx.x;
    const int bm = blockIdx.x * BM, bn = blockIdx.y * BM;
    const int arowi = bm + (tid >> 1);
    const float* arow = (arowi < R_) ? rc + (size_t)arowi * D_
                                     : utt + (size_t)(arowi - R_) * D_;
    const float* brow = W + (size_t)(bn + (tid >> 1)) * D_;
    float c[4][4][4];
#pragma unroll
    for (int a = 0; a < 4; a++)
#pragma unroll
        for (int b = 0; b < 4; b++)
#pragma unroll
            for (int d = 0; d < 4; d++) c[a][b][d] = 0.f;
    mma_gemm_loop(arow, brow, As, Bs, tid, c);
    const int lane = tid & 31;
    const int wid = tid >> 5;
    const int wm = (wid >> 2) * 64, wn = (wid & 3) * 32;
    const int gr = lane >> 2, tg = lane & 3;
#pragma unroll
    for (int ni = 0; ni < 4; ni++) {
        int col = bn + wn + ni * 8 + tg * 2;
        float2 bb = *(const float2*)(bias + col);
#pragma unroll
        for (int mi = 0; mi < 4; mi++) {
            int row = bm + wm + mi * 16 + gr;
            *(float2*)(g_query + (size_t)row * D_ + col) =
                make_float2(c[mi][ni][0] + bb.x, c[mi][ni][1] + bb.y);
            *(float2*)(g_query + (size_t)(row + 8) * D_ + col) =
                make_float2(c[mi][ni][2] + bb.x, c[mi][ni][3] + bb.y);
        }
    }
}

// kv = concat(mem, rc, utt) @ Wkv^T + bkv -> scattered into key/value buffers
__global__ __launch_bounds__(256) void gemm_kv_kernel(const float* __restrict__ mem,
                                                      const float* __restrict__ rc,
                                                      const float* __restrict__ utt,
                                                      const float* __restrict__ W,
                                                      const float* __restrict__ bias,
                                                      float* __restrict__ keyBuf,
                                                      float* __restrict__ valBuf) {
    __shared__ __align__(16) unsigned As[BM * KSTR];
    __shared__ __align__(16) unsigned Bs[BM * KSTR];
    const int tid = threadIdx.x;
    const int bm = blockIdx.x * BM, bn = blockIdx.y * BM;
    const int arowi = bm + (tid >> 1);
    const float* arow = (arowi < M_)      ? mem + (size_t)arowi * D_
                      : (arowi < M_ + R_) ? rc + (size_t)(arowi - M_) * D_
                                          : utt + (size_t)(arowi - M_ - R_) * D_;
    const float* brow = W + (size_t)(bn + (tid >> 1)) * D_;
    float c[4][4][4];
#pragma unroll
    for (int a = 0; a < 4; a++)
#pragma unroll
        for (int b = 0; b < 4; b++)
#pragma unroll
            for (int d = 0; d < 4; d++) c[a][b][d] = 0.f;
    mma_gemm_loop(arow, brow, As, Bs, tid, c);
    const int lane = tid & 31;
    const int wid = tid >> 5;
    const int wm = (wid >> 2) * 64, wn = (wid & 3) * 32;
    const int gr = lane >> 2, tg = lane & 3;
    float* obase = (bn < D_) ? keyBuf : valBuf;
    const int cb = (bn < D_) ? bn : bn - D_;
#pragma unroll
    for (int ni = 0; ni < 4; ni++) {
        int col = cb + wn + ni * 8 + tg * 2;
        float2 bb = *(const float2*)(bias + bn + wn + ni * 8 + tg * 2);
#pragma unroll
        for (int mi = 0; mi < 4; mi++) {
            int row0 = bm + wm + mi * 16 + gr;
            int ro0 = (row0 < M_ + R_) ? row0 : row0 + L_;
            int row1 = row0 + 8;
            int ro1 = (row1 < M_ + R_) ? row1 : row1 + L_;
            *(float2*)(obase + (size_t)ro0 * D_ + col) =
                make_float2(c[mi][ni][0] + bb.x, c[mi][ni][1] + bb.y);
            *(float2*)(obase + (size_t)ro1 * D_ + col) =
                make_float2(c[mi][ni][2] + bb.x, c[mi][ni][3] + bb.y);
        }
    }
}

// out = g_attn @ Wo^T + bo
__global__ __launch_bounds__(256) void gemm_o_kernel(const float* __restrict__ W,
                                                     const float* __restrict__ bias,
                                                     float* __restrict__ outBuf) {
    __shared__ __align__(16) unsigned As[BM * KSTR];
    __shared__ __align__(16) unsigned Bs[BM * KSTR];
    const int tid = threadIdx.x;
    const int bm = blockIdx.x * BM, bn = blockIdx.y * BM;
    const float* arow = g_attn + (size_t)(bm + (tid >> 1)) * D_;
    const float* brow = W + (size_t)(bn + (tid >> 1)) * D_;
    float c[4][4][4];
#pragma unroll
    for (int a = 0; a < 4; a++)
#pragma unroll
        for (int b = 0; b < 4; b++)
#pragma unroll
            for (int d = 0; d < 4; d++) c[a][b][d] = 0.f;
    mma_gemm_loop(arow, brow, As, Bs, tid, c);
    const int lane = tid & 31;
    const int wid = tid >> 5;
    const int wm = (wid >> 2) * 64, wn = (wid & 3) * 32;
    const int gr = lane >> 2, tg = lane & 3;
#pragma unroll
    for (int ni = 0; ni < 4; ni++) {
        int col = bn + wn + ni * 8 + tg * 2;
        float2 bb = *(const float2*)(bias + col);
#pragma unroll
        for (int mi = 0; mi < 4; mi++) {
            int row = bm + wm + mi * 16 + gr;
            *(float2*)(outBuf + (size_t)row * D_ + col) =
                make_float2(c[mi][ni][0] + bb.x, c[mi][ni][1] + bb.y);
            *(float2*)(outBuf + (size_t)(row + 8) * D_ + col) =
                make_float2(c[mi][ni][2] + bb.x, c[mi][ni][3] + bb.y);
        }
    }
}

// ===========================================================================
// Flash attention v4: tf32 tensor-core S and P@V.
// Block = 64 q-rows x one head, 128 threads = 4 warps; warp w owns q-rows
// [w*16, w*16+16). kv tile 64. Q held in registers as tf32 A-fragments.
// Smem: Ks[64][68], Vs[64][72], Ps[64][68] (tf32 bits) -> all fragment
// accesses bank-conflict-free. P is warp-local (only __syncwarp between
// P write and P@V). 52 KB smem, 3 CTAs/SM.
// ===========================================================================
#define AT_TK 64
#define KS_STR 68   // [n][k] access: bank = 4*gr+tg -> 32 distinct
#define VS_STR 72   // [k][n] access: bank = 8*tg+gr -> 32 distinct

__global__ __launch_bounds__(128, 3) void attn_kernel(const float* __restrict__ Kg,
                                                      const float* __restrict__ Vg) {
    extern __shared__ __align__(16) unsigned smu[];
    unsigned* Ks = smu;                    // [64][KS_STR]
    unsigned* Vs = Ks + 64 * KS_STR;       // [64][VS_STR]
    unsigned* Ps = Vs + 64 * VS_STR;       // [64][KS_STR]

    const int tid = threadIdx.x;
    const int lane = tid & 31, wid = tid >> 5;
    const int gr = lane >> 2, tg = lane & 3;
    const int wm = wid * 16;
    const int qbase = blockIdx.x * 64;
    const int hoff = blockIdx.y * HD;
    const int row_lo = qbase + wm + gr;
    const int row_hi = row_lo + 8;

    // Q fragments for the whole kernel (pre-scaled by 1/sqrt(64), tf32)
    unsigned qf[8][4];
#pragma unroll
    for (int ks = 0; ks < 8; ks++) {
        int c = hoff + ks * 8 + tg;
        qf[ks][0] = f2tf(g_query[(size_t)row_lo * D_ + c] * 0.125f);
        qf[ks][1] = f2tf(g_query[(size_t)row_hi * D_ + c] * 0.125f);
        qf[ks][2] = f2tf(g_query[(size_t)row_lo * D_ + c + 4] * 0.125f);
        qf[ks][3] = f2tf(g_query[(size_t)row_hi * D_ + c + 4] * 0.125f);
    }

    float o[8][4];
#pragma unroll
    for (int i = 0; i < 8; i++)
#pragma unroll
        for (int j = 0; j < 4; j++) o[i][j] = 0.f;
    float m_lo = -INFINITY, m_hi = -INFINITY, l_lo = 0.f, l_hi = 0.f;

    for (int kt = 0; kt < KVL; kt += AT_TK) {
        __syncthreads();  // all warps done with prev Ks/Vs
        // Load K, V tiles (64x64 each), convert to tf32
#pragma unroll
        for (int jj = 0; jj < 8; jj++) {
            int id = jj * 128 + tid;
            int r = id >> 4;
            int dseg = (id & 15) * 4;
            float4 k4 = *(const float4*)(Kg + (size_t)(kt + r) * D_ + hoff + dseg);
            *(uint4*)(Ks + r * KS_STR + dseg) =
                make_uint4(f2tf(k4.x), f2tf(k4.y), f2tf(k4.z), f2tf(k4.w));
            float4 v4 = *(const float4*)(Vg + (size_t)(kt + r) * D_ + hoff + dseg);
            *(uint4*)(Vs + r * VS_STR + dseg) =
                make_uint4(f2tf(v4.x), f2tf(v4.y), f2tf(v4.z), f2tf(v4.w));
        }
        __syncthreads();

        // ---- S = Q @ K^T : warp computes 16 rows x 64 kv cols ----
        float s[8][4];
#pragma unroll
        for (int i = 0; i < 8; i++)
#pragma unroll
            for (int j = 0; j < 4; j++) s[i][j] = 0.f;
#pragma unroll
        for (int ni = 0; ni < 8; ni++) {
            const unsigned* bb = Ks + (ni * 8 + gr) * KS_STR + tg;
#pragma unroll
            for (int ks = 0; ks < 8; ks++) {
                unsigned b0 = bb[ks * 8];
                unsigned b1 = bb[ks * 8 + 4];
                mma_tf32(s[ni], qf[ks][0], qf[ks][1], qf[ks][2], qf[ks][3], b0, b1);
            }
        }

        // ---- online softmax (rows gr and gr+8; stats within quad) ----
        float mt_lo = -INFINITY, mt_hi = -INFINITY;
#pragma unroll
        for (int ni = 0; ni < 8; ni++) {
            mt_lo = fmaxf(mt_lo, fmaxf(s[ni][0], s[ni][1]));
            mt_hi = fmaxf(mt_hi, fmaxf(s[ni][2], s[ni][3]));
        }
        mt_lo = fmaxf(mt_lo, __shfl_xor_sync(0xffffffffu, mt_lo, 1));
        mt_lo = fmaxf(mt_lo, __shfl_xor_sync(0xffffffffu, mt_lo, 2));
        mt_hi = fmaxf(mt_hi, __shfl_xor_sync(0xffffffffu, mt_hi, 1));
        mt_hi = fmaxf(mt_hi, __shfl_xor_sync(0xffffffffu, mt_hi, 2));
        float mnew_lo = fmaxf(m_lo, mt_lo);
        float mnew_hi = fmaxf(m_hi, mt_hi);
        float alpha_lo = __expf(m_lo - mnew_lo);
        float alpha_hi = __expf(m_hi - mnew_hi);
        float sum_lo = 0.f, sum_hi = 0.f;
#pragma unroll
        for (int ni = 0; ni < 8; ni++) {
            s[ni][0] = __expf(s[ni][0] - mnew_lo);
            s[ni][1] = __expf(s[ni][1] - mnew_lo);
            s[ni][2] = __expf(s[ni][2] - mnew_hi);
            s[ni][3] = __expf(s[ni][3] - mnew_hi);
            sum_lo += s[ni][0] + s[ni][1];
            sum_hi += s[ni][2] + s[ni][3];
        }
        sum_lo += __shfl_xor_sync(0xffffffffu, sum_lo, 1);
        sum_lo += __shfl_xor_sync(0xffffffffu, sum_lo, 2);
        sum_hi += __shfl_xor_sync(0xffffffffu, sum_hi, 1);
        sum_hi += __shfl_xor_sync(0xffffffffu, sum_hi, 2);
        l_lo = l_lo * alpha_lo + sum_lo;
        l_hi = l_hi * alpha_hi + sum_hi;
        m_lo = mnew_lo;
        m_hi = mnew_hi;
#pragma unroll
        for (int ni = 0; ni < 8; ni++) {
            o[ni][0] *= alpha_lo; o[ni][1] *= alpha_lo;
            o[ni][2] *= alpha_hi; o[ni][3] *= alpha_hi;
        }

        // ---- write P (warp-local rows) as tf32 ----
#pragma unroll
        for (int ni = 0; ni < 8; ni++) {
            int cc = ni * 8 + 2 * tg;
            *(uint2*)(Ps + (wm + gr) * KS_STR + cc) =
                make_uint2(f2tf(s[ni][0]), f2tf(s[ni][1]));
            *(uint2*)(Ps + (wm + gr + 8) * KS_STR + cc) =
                make_uint2(f2tf(s[ni][2]), f2tf(s[ni][3]));
        }
        __syncwarp();

        // ---- O += P @ V : warp computes 16 rows x 64 dims ----
#pragma unroll
        for (int ks = 0; ks < 8; ks++) {
            const unsigned* pa = Ps + (wm + gr) * KS_STR + ks * 8 + tg;
            unsigned a0 = pa[0];
            unsigned a1 = pa[8 * KS_STR];
            unsigned a2 = pa[4];
            unsigned a3 = pa[8 * KS_STR + 4];
            const unsigned* vb = Vs + (ks * 8 + tg) * VS_STR + gr;
#pragma unroll
            for (int ni = 0; ni < 8; ni++) {
                unsigned b0 = vb[ni * 8];
                unsigned b1 = vb[4 * VS_STR + ni * 8];
                mma_tf32(o[ni], a0, a1, a2, a3, b0, b1);
            }
        }
    }

    // normalize and write
    float inv_lo = 1.0f / l_lo;
    float inv_hi = 1.0f / l_hi;
#pragma unroll
    for (int ni = 0; ni < 8; ni++) {
        int col = hoff + ni * 8 + 2 * tg;
        *(float2*)(g_attn + (size_t)row_lo * D_ + col) =
            make_float2(o[ni][0] * inv_lo, o[ni][1] * inv_lo);
        *(float2*)(g_attn + (size_t)row_hi * D_ + col) =
            make_float2(o[ni][2] * inv_hi, o[ni][3] * inv_hi);
    }
}

#define ATTN_SMEM ((64 * KS_STR + 64 * VS_STR + 64 * KS_STR) * (int)sizeof(unsigned))

// ---------------------------------------------------------------------------
extern "C" void kernel_launch(void* const* d_in, const int* in_sizes, int n_in,
                              void* d_out, int out_size) {
    const float* utt = (const float*)d_in[0];
    const float* rc  = (const float*)d_in[1];
    const float* mem = (const float*)d_in[2];
    const float* lck = (const float*)d_in[3];
    const float* lcv = (const float*)d_in[4];
    const float* Wq  = (const float*)d_in[5];
    const float* bq  = (const float*)d_in[6];
    const float* Wkv = (const float*)d_in[7];
    const float* bkv = (const float*)d_in[8];
    const float* Wo  = (const float*)d_in[9];
    const float* bo  = (const float*)d_in[10];

    float* outBuf = (float*)d_out;                       // [2304,1024]
    float* keyBuf = outBuf + (size_t)QL * D_;            // [3840,1024]
    float* valBuf = keyBuf + (size_t)KVL * D_;           // [3840,1024]

    cudaFuncSetAttribute(attn_kernel, cudaFuncAttributeMaxDynamicSharedMemorySize,
                         ATTN_SMEM);

    gemm_q_kernel<<<dim3(QL / BM, D_ / BM), 256>>>(rc, utt, Wq, bq);
    gemm_kv_kernel<<<dim3((M_ + R_ + U_) / BM, 2 * D_ / BM), 256>>>(
        mem, rc, utt, Wkv, bkv, keyBuf, valBuf);
    cudaMemcpyAsync(keyBuf + (size_t)(M_ + R_) * D_, lck,
                    (size_t)L_ * D_ * sizeof(float), cudaMemcpyDeviceToDevice);
    cudaMemcpyAsync(valBuf + (size_t)(M_ + R_) * D_, lcv,
                    (size_t)L_ * D_ * sizeof(float), cudaMemcpyDeviceToDevice);
    attn_kernel<<<dim3(QL / 64, NH), 128, ATTN_SMEM>>>(keyBuf, valBuf);
    gemm_o_kernel<<<dim3(QL / BM, D_ / BM), 256>>>(Wo, bo, outBuf);
}

// round 10
// speedup vs baseline: 11.8353x; 1.5853x over previous
#include <cuda_runtime.h>
#include <cuda_bf16.h>
#include <math.h>

#define D_   1024
#define U_   2048
#define R_   256
#define L_   1024
#define M_   512
#define QL   2304   // U + R
#define KVL  3840   // M + R + L + U
#define NH   16
#define HD   64

// Scratch
__device__ float g_query[(size_t)QL * D_];
__device__ float g_attn[(size_t)QL * D_];

// ===========================================================================
// tf32 tensor-core GEMM: C(128x128) = A @ B^T (+bias), both row-major K-contig
// 256 threads = 8 warps (2m x 4n), warp tile 64x32, mma.m16n8k8.tf32.
// ===========================================================================
#define BM 128
#define BK 32
#define KSTR 36   // smem stride words -> fragment LDS conflict-free

__device__ __forceinline__ unsigned f2tf(float f) {
    unsigned r; asm("cvt.rna.tf32.f32 %0, %1;" : "=r"(r) : "f"(f)); return r;
}

__device__ __forceinline__ void mma_tf32(float c[4], unsigned a0, unsigned a1,
                                         unsigned a2, unsigned a3,
                                         unsigned b0, unsigned b1) {
    asm("mma.sync.aligned.m16n8k8.row.col.f32.tf32.tf32.f32 "
        "{%0,%1,%2,%3}, {%4,%5,%6,%7}, {%8,%9}, {%0,%1,%2,%3};"
        : "+f"(c[0]), "+f"(c[1]), "+f"(c[2]), "+f"(c[3])
        : "r"(a0), "r"(a1), "r"(a2), "r"(a3), "r"(b0), "r"(b1));
}

__device__ __forceinline__ void mma_gemm_loop(const float* __restrict__ arow,
                                              const float* __restrict__ brow,
                                              unsigned* As, unsigned* Bs, int tid,
                                              float c[4][4][4]) {
    const int lseg = (tid & 1) * 16;
    const int lrow = tid >> 1;
    const int lane = tid & 31;
    const int wid = tid >> 5;
    const int wm = (wid >> 2) * 64;
    const int wn = (wid & 3) * 32;
    const int gr = lane >> 2, tg = lane & 3;
    for (int kt = 0; kt < D_; kt += BK) {
        float4 a[4], b[4];
#pragma unroll
        for (int j = 0; j < 4; j++) {
            a[j] = *(const float4*)(arow + kt + lseg + 4 * j);
            b[j] = *(const float4*)(brow + kt + lseg + 4 * j);
        }
        __syncthreads();
#pragma unroll
        for (int j = 0; j < 4; j++) {
            *(uint4*)(As + lrow * KSTR + lseg + 4 * j) =
                make_uint4(f2tf(a[j].x), f2tf(a[j].y), f2tf(a[j].z), f2tf(a[j].w));
            *(uint4*)(Bs + lrow * KSTR + lseg + 4 * j) =
                make_uint4(f2tf(b[j].x), f2tf(b[j].y), f2tf(b[j].z), f2tf(b[j].w));
        }
        __syncthreads();
#pragma unroll
        for (int ks = 0; ks < 4; ks++) {
            unsigned af[4][4], bf[4][2];
#pragma unroll
            for (int mi = 0; mi < 4; mi++) {
                const unsigned* ab = As + (wm + mi * 16 + gr) * KSTR + ks * 8 + tg;
                af[mi][0] = ab[0];
                af[mi][1] = ab[8 * KSTR];
                af[mi][2] = ab[4];
                af[mi][3] = ab[8 * KSTR + 4];
            }
#pragma unroll
            for (int ni = 0; ni < 4; ni++) {
                const unsigned* bb = Bs + (wn + ni * 8 + gr) * KSTR + ks * 8 + tg;
                bf[ni][0] = bb[0];
                bf[ni][1] = bb[4];
            }
#pragma unroll
            for (int mi = 0; mi < 4; mi++)
#pragma unroll
                for (int ni = 0; ni < 4; ni++)
                    mma_tf32(c[mi][ni], af[mi][0], af[mi][1], af[mi][2], af[mi][3],
                             bf[ni][0], bf[ni][1]);
        }
    }
}

// query = concat(rc, utt) @ Wq^T + bq -> g_query
__global__ __launch_bounds__(256) void gemm_q_kernel(const float* __restrict__ rc,
                                                     const float* __restrict__ utt,
                                                     const float* __restrict__ W,
                                                     const float* __restrict__ bias) {
    __shared__ __align__(16) unsigned As[BM * KSTR];
    __shared__ __align__(16) unsigned Bs[BM * KSTR];
    const int tid = threadIdx.x;
    const int bm = blockIdx.x * BM, bn = blockIdx.y * BM;
    const int arowi = bm + (tid >> 1);
    const float* arow = (arowi < R_) ? rc + (size_t)arowi * D_
                                     : utt + (size_t)(arowi - R_) * D_;
    const float* brow = W + (size_t)(bn + (tid >> 1)) * D_;
    float c[4][4][4];
#pragma unroll
    for (int a = 0; a < 4; a++)
#pragma unroll
        for (int b = 0; b < 4; b++)
#pragma unroll
            for (int d = 0; d < 4; d++) c[a][b][d] = 0.f;
    mma_gemm_loop(arow, brow, As, Bs, tid, c);
    const int lane = tid & 31;
    const int wid = tid >> 5;
    const int wm = (wid >> 2) * 64, wn = (wid & 3) * 32;
    const int gr = lane >> 2, tg = lane & 3;
#pragma unroll
    for (int ni = 0; ni < 4; ni++) {
        int col = bn + wn + ni * 8 + tg * 2;
        float2 bb = *(const float2*)(bias + col);
#pragma unroll
        for (int mi = 0; mi < 4; mi++) {
            int row = bm + wm + mi * 16 + gr;
            *(float2*)(g_query + (size_t)row * D_ + col) =
                make_float2(c[mi][ni][0] + bb.x, c[mi][ni][1] + bb.y);
            *(float2*)(g_query + (size_t)(row + 8) * D_ + col) =
                make_float2(c[mi][ni][2] + bb.x, c[mi][ni][3] + bb.y);
        }
    }
}

// kv = concat(mem, rc, utt) @ Wkv^T + bkv -> scattered into key/value buffers
__global__ __launch_bounds__(256) void gemm_kv_kernel(const float* __restrict__ mem,
                                                      const float* __restrict__ rc,
                                                      const float* __restrict__ utt,
                                                      const float* __restrict__ W,
                                                      const float* __restrict__ bias,
                                                      float* __restrict__ keyBuf,
                                                      float* __restrict__ valBuf) {
    __shared__ __align__(16) unsigned As[BM * KSTR];
    __shared__ __align__(16) unsigned Bs[BM * KSTR];
    const int tid = threadIdx.x;
    const int bm = blockIdx.x * BM, bn = blockIdx.y * BM;
    const int arowi = bm + (tid >> 1);
    const float* arow = (arowi < M_)      ? mem + (size_t)arowi * D_
                      : (arowi < M_ + R_) ? rc + (size_t)(arowi - M_) * D_
                                          : utt + (size_t)(arowi - M_ - R_) * D_;
    const float* brow = W + (size_t)(bn + (tid >> 1)) * D_;
    float c[4][4][4];
#pragma unroll
    for (int a = 0; a < 4; a++)
#pragma unroll
        for (int b = 0; b < 4; b++)
#pragma unroll
            for (int d = 0; d < 4; d++) c[a][b][d] = 0.f;
    mma_gemm_loop(arow, brow, As, Bs, tid, c);
    const int lane = tid & 31;
    const int wid = tid >> 5;
    const int wm = (wid >> 2) * 64, wn = (wid & 3) * 32;
    const int gr = lane >> 2, tg = lane & 3;
    float* obase = (bn < D_) ? keyBuf : valBuf;
    const int cb = (bn < D_) ? bn : bn - D_;
#pragma unroll
    for (int ni = 0; ni < 4; ni++) {
        int col = cb + wn + ni * 8 + tg * 2;
        float2 bb = *(const float2*)(bias + bn + wn + ni * 8 + tg * 2);
#pragma unroll
        for (int mi = 0; mi < 4; mi++) {
            int row0 = bm + wm + mi * 16 + gr;
            int ro0 = (row0 < M_ + R_) ? row0 : row0 + L_;
            int row1 = row0 + 8;
            int ro1 = (row1 < M_ + R_) ? row1 : row1 + L_;
            *(float2*)(obase + (size_t)ro0 * D_ + col) =
                make_float2(c[mi][ni][0] + bb.x, c[mi][ni][1] + bb.y);
            *(float2*)(obase + (size_t)ro1 * D_ + col) =
                make_float2(c[mi][ni][2] + bb.x, c[mi][ni][3] + bb.y);
        }
    }
}

// out = g_attn @ Wo^T + bo
__global__ __launch_bounds__(256) void gemm_o_kernel(const float* __restrict__ W,
                                                     const float* __restrict__ bias,
                                                     float* __restrict__ outBuf) {
    __shared__ __align__(16) unsigned As[BM * KSTR];
    __shared__ __align__(16) unsigned Bs[BM * KSTR];
    const int tid = threadIdx.x;
    const int bm = blockIdx.x * BM, bn = blockIdx.y * BM;
    const float* arow = g_attn + (size_t)(bm + (tid >> 1)) * D_;
    const float* brow = W + (size_t)(bn + (tid >> 1)) * D_;
    float c[4][4][4];
#pragma unroll
    for (int a = 0; a < 4; a++)
#pragma unroll
        for (int b = 0; b < 4; b++)
#pragma unroll
            for (int d = 0; d < 4; d++) c[a][b][d] = 0.f;
    mma_gemm_loop(arow, brow, As, Bs, tid, c);
    const int lane = tid & 31;
    const int wid = tid >> 5;
    const int wm = (wid >> 2) * 64, wn = (wid & 3) * 32;
    const int gr = lane >> 2, tg = lane & 3;
#pragma unroll
    for (int ni = 0; ni < 4; ni++) {
        int col = bn + wn + ni * 8 + tg * 2;
        float2 bb = *(const float2*)(bias + col);
#pragma unroll
        for (int mi = 0; mi < 4; mi++) {
            int row = bm + wm + mi * 16 + gr;
            *(float2*)(outBuf + (size_t)row * D_ + col) =
                make_float2(c[mi][ni][0] + bb.x, c[mi][ni][1] + bb.y);
            *(float2*)(outBuf + (size_t)(row + 8) * D_ + col) =
                make_float2(c[mi][ni][2] + bb.x, c[mi][ni][3] + bb.y);
        }
    }
}

// ===========================================================================
// Flash attention v5: tf32 tensor-core S and P@V, TQ=128 (K/V reuse 2x).
// Block = 128 q-rows x one head, 256 threads = 8 warps; warp w owns q-rows
// [w*16, w*16+16). kv tile 64. Q held in registers as tf32 A-fragments.
// Smem: Ks[64][68], Vs[64][72], Ps[128][68] = 69 KB -> 2 CTAs/SM.
// P is warp-local (only __syncwarp between P write and P@V).
// ===========================================================================
#define AT_TQ 128
#define AT_TK 64
#define KS_STR 68   // [n][k] access: bank = 4*gr+tg -> 32 distinct
#define VS_STR 72   // [k][n] access: bank = 8*tg+gr -> 32 distinct

__global__ __launch_bounds__(256, 2) void attn_kernel(const float* __restrict__ Kg,
                                                      const float* __restrict__ Vg) {
    extern __shared__ __align__(16) unsigned smu[];
    unsigned* Ks = smu;                    // [64][KS_STR]
    unsigned* Vs = Ks + AT_TK * KS_STR;    // [64][VS_STR]
    unsigned* Ps = Vs + AT_TK * VS_STR;    // [128][KS_STR]

    const int tid = threadIdx.x;
    const int lane = tid & 31, wid = tid >> 5;
    const int gr = lane >> 2, tg = lane & 3;
    const int wm = wid * 16;               // warp's q-row strip within block
    const int qbase = blockIdx.x * AT_TQ;
    const int hoff = blockIdx.y * HD;
    const int row_lo = qbase + wm + gr;
    const int row_hi = row_lo + 8;

    // Q fragments for the whole kernel (pre-scaled by 1/sqrt(64), tf32)
    unsigned qf[8][4];
#pragma unroll
    for (int ks = 0; ks < 8; ks++) {
        int c = hoff + ks * 8 + tg;
        qf[ks][0] = f2tf(g_query[(size_t)row_lo * D_ + c] * 0.125f);
        qf[ks][1] = f2tf(g_query[(size_t)row_hi * D_ + c] * 0.125f);
        qf[ks][2] = f2tf(g_query[(size_t)row_lo * D_ + c + 4] * 0.125f);
        qf[ks][3] = f2tf(g_query[(size_t)row_hi * D_ + c + 4] * 0.125f);
    }

    float o[8][4];
#pragma unroll
    for (int i = 0; i < 8; i++)
#pragma unroll
        for (int j = 0; j < 4; j++) o[i][j] = 0.f;
    float m_lo = -INFINITY, m_hi = -INFINITY, l_lo = 0.f, l_hi = 0.f;

    for (int kt = 0; kt < KVL; kt += AT_TK) {
        __syncthreads();  // all warps done with prev Ks/Vs
        // Load K, V tiles (64x64 each), convert to tf32; 4 float4/thread/tensor
#pragma unroll
        for (int jj = 0; jj < 4; jj++) {
            int id = jj * 256 + tid;
            int r = id >> 4;
            int dseg = (id & 15) * 4;
            float4 k4 = *(const float4*)(Kg + (size_t)(kt + r) * D_ + hoff + dseg);
            *(uint4*)(Ks + r * KS_STR + dseg) =
                make_uint4(f2tf(k4.x), f2tf(k4.y), f2tf(k4.z), f2tf(k4.w));
            float4 v4 = *(const float4*)(Vg + (size_t)(kt + r) * D_ + hoff + dseg);
            *(uint4*)(Vs + r * VS_STR + dseg) =
                make_uint4(f2tf(v4.x), f2tf(v4.y), f2tf(v4.z), f2tf(v4.w));
        }
        __syncthreads();

        // ---- S = Q @ K^T : warp computes 16 rows x 64 kv cols ----
        float s[8][4];
#pragma unroll
        for (int i = 0; i < 8; i++)
#pragma unroll
            for (int j = 0; j < 4; j++) s[i][j] = 0.f;
#pragma unroll
        for (int ni = 0; ni < 8; ni++) {
            const unsigned* bb = Ks + (ni * 8 + gr) * KS_STR + tg;
#pragma unroll
            for (int ks = 0; ks < 8; ks++) {
                unsigned b0 = bb[ks * 8];
                unsigned b1 = bb[ks * 8 + 4];
                mma_tf32(s[ni], qf[ks][0], qf[ks][1], qf[ks][2], qf[ks][3], b0, b1);
            }
        }

        // ---- online softmax (rows gr and gr+8; stats within quad) ----
        float mt_lo = -INFINITY, mt_hi = -INFINITY;
#pragma unroll
        for (int ni = 0; ni < 8; ni++) {
            mt_lo = fmaxf(mt_lo, fmaxf(s[ni][0], s[ni][1]));
            mt_hi = fmaxf(mt_hi, fmaxf(s[ni][2], s[ni][3]));
        }
        mt_lo = fmaxf(mt_lo, __shfl_xor_sync(0xffffffffu, mt_lo, 1));
        mt_lo = fmaxf(mt_lo, __shfl_xor_sync(0xffffffffu, mt_lo, 2));
        mt_hi = fmaxf(mt_hi, __shfl_xor_sync(0xffffffffu, mt_hi, 1));
        mt_hi = fmaxf(mt_hi, __shfl_xor_sync(0xffffffffu, mt_hi, 2));
        float mnew_lo = fmaxf(m_lo, mt_lo);
        float mnew_hi = fmaxf(m_hi, mt_hi);
        float alpha_lo = __expf(m_lo - mnew_lo);
        float alpha_hi = __expf(m_hi - mnew_hi);
        float sum_lo = 0.f, sum_hi = 0.f;
#pragma unroll
        for (int ni = 0; ni < 8; ni++) {
            s[ni][0] = __expf(s[ni][0] - mnew_lo);
            s[ni][1] = __expf(s[ni][1] - mnew_lo);
            s[ni][2] = __expf(s[ni][2] - mnew_hi);
            s[ni][3] = __expf(s[ni][3] - mnew_hi);
            sum_lo += s[ni][0] + s[ni][1];
            sum_hi += s[ni][2] + s[ni][3];
        }
        sum_lo += __shfl_xor_sync(0xffffffffu, sum_lo, 1);
        sum_lo += __shfl_xor_sync(0xffffffffu, sum_lo, 2);
        sum_hi += __shfl_xor_sync(0xffffffffu, sum_hi, 1);
        sum_hi += __shfl_xor_sync(0xffffffffu, sum_hi, 2);
        l_lo = l_lo * alpha_lo + sum_lo;
        l_hi = l_hi * alpha_hi + sum_hi;
        m_lo = mnew_lo;
        m_hi = mnew_hi;
#pragma unroll
        for (int ni = 0; ni < 8; ni++) {
            o[ni][0] *= alpha_lo; o[ni][1] *= alpha_lo;
            o[ni][2] *= alpha_hi; o[ni][3] *= alpha_hi;
        }

        // ---- write P (warp-local rows) as tf32 ----
#pragma unroll
        for (int ni = 0; ni < 8; ni++) {
            int cc = ni * 8 + 2 * tg;
            *(uint2*)(Ps + (wm + gr) * KS_STR + cc) =
                make_uint2(f2tf(s[ni][0]), f2tf(s[ni][1]));
            *(uint2*)(Ps + (wm + gr + 8) * KS_STR + cc) =
                make_uint2(f2tf(s[ni][2]), f2tf(s[ni][3]));
        }
        __syncwarp();

        // ---- O += P @ V : warp computes 16 rows x 64 dims ----
#pragma unroll
        for (int ks = 0; ks < 8; ks++) {
            const unsigned* pa = Ps + (wm + gr) * KS_STR + ks * 8 + tg;
            unsigned a0 = pa[0];
            unsigned a1 = pa[8 * KS_STR];
            unsigned a2 = pa[4];
            unsigned a3 = pa[8 * KS_STR + 4];
            const unsigned* vb = Vs + (ks * 8 + tg) * VS_STR + gr;
#pragma unroll
            for (int ni = 0; ni < 8; ni++) {
                unsigned b0 = vb[ni * 8];
                unsigned b1 = vb[4 * VS_STR + ni * 8];
                mma_tf32(o[ni], a0, a1, a2, a3, b0, b1);
            }
        }
    }

    // normalize and write
    float inv_lo = 1.0f / l_lo;
    float inv_hi = 1.0f / l_hi;
#pragma unroll
    for (int ni = 0; ni < 8; ni++) {
        int col = hoff + ni * 8 + 2 * tg;
        *(float2*)(g_attn + (size_t)row_lo * D_ + col) =
            make_float2(o[ni][0] * inv_lo, o[ni][1] * inv_lo);
        *(float2*)(g_attn + (size_t)row_hi * D_ + col) =
            make_float2(o[ni][2] * inv_hi, o[ni][3] * inv_hi);
    }
}

#define ATTN_SMEM ((AT_TK * KS_STR + AT_TK * VS_STR + AT_TQ * KS_STR) * (int)sizeof(unsigned))

// ---------------------------------------------------------------------------
extern "C" void kernel_launch(void* const* d_in, const int* in_sizes, int n_in,
                              void* d_out, int out_size) {
    const float* utt = (const float*)d_in[0];
    const float* rc  = (const float*)d_in[1];
    const float* mem = (const float*)d_in[2];
    const float* lck = (const float*)d_in[3];
    const float* lcv = (const float*)d_in[4];
    const float* Wq  = (const float*)d_in[5];
    const float* bq  = (const float*)d_in[6];
    const float* Wkv = (const float*)d_in[7];
    const float* bkv = (const float*)d_in[8];
    const float* Wo  = (const float*)d_in[9];
    const float* bo  = (const float*)d_in[10];

    float* outBuf = (float*)d_out;                       // [2304,1024]
    float* keyBuf = outBuf + (size_t)QL * D_;            // [3840,1024]
    float* valBuf = keyBuf + (size_t)KVL * D_;           // [3840,1024]

    cudaFuncSetAttribute(attn_kernel, cudaFuncAttributeMaxDynamicSharedMemorySize,
                         ATTN_SMEM);

    gemm_q_kernel<<<dim3(QL / BM, D_ / BM), 256>>>(rc, utt, Wq, bq);
    gemm_kv_kernel<<<dim3((M_ + R_ + U_) / BM, 2 * D_ / BM), 256>>>(
        mem, rc, utt, Wkv, bkv, keyBuf, valBuf);
    cudaMemcpyAsync(keyBuf + (size_t)(M_ + R_) * D_, lck,
                    (size_t)L_ * D_ * sizeof(float), cudaMemcpyDeviceToDevice);
    cudaMemcpyAsync(valBuf + (size_t)(M_ + R_) * D_, lcv,
                    (size_t)L_ * D_ * sizeof(float), cudaMemcpyDeviceToDevice);
    attn_kernel<<<dim3(QL / AT_TQ, NH), 256, ATTN_SMEM>>>(keyBuf, valBuf);
    gemm_o_kernel<<<dim3(QL / BM, D_ / BM), 256>>>(Wo, bo, outBuf);
}

// round 11
// speedup vs baseline: 12.7525x; 1.0775x over previous
#include <cuda_runtime.h>
#include <cuda_bf16.h>
#include <math.h>

#define D_   1024
#define U_   2048
#define R_   256
#define L_   1024
#define M_   512
#define QL   2304   // U + R
#define KVL  3840   // M + R + L + U
#define NH   16
#define HD   64

// Scratch
__device__ float g_query[(size_t)QL * D_];
__device__ float g_attn[(size_t)QL * D_];

// ===========================================================================
// tf32 tensor-core GEMM: C(128x64) = A @ B^T (+bias), both row-major K-contig
// 256 threads = 8 warps (4m x 2n), warp tile 32x32, mma.m16n8k8.tf32.
// Smaller BN -> 2-4 CTAs/SM (round-9 config was grid-starved at 1 CTA/SM).
// ===========================================================================
#define BM 128
#define BN 64
#define BK 32
#define KSTR 36   // smem stride words -> fragment LDS conflict-free

__device__ __forceinline__ unsigned f2tf(float f) {
    unsigned r; asm("cvt.rna.tf32.f32 %0, %1;" : "=r"(r) : "f"(f)); return r;
}

__device__ __forceinline__ void mma_tf32(float c[4], unsigned a0, unsigned a1,
                                         unsigned a2, unsigned a3,
                                         unsigned b0, unsigned b1) {
    asm("mma.sync.aligned.m16n8k8.row.col.f32.tf32.tf32.f32 "
        "{%0,%1,%2,%3}, {%4,%5,%6,%7}, {%8,%9}, {%0,%1,%2,%3};"
        : "+f"(c[0]), "+f"(c[1]), "+f"(c[2]), "+f"(c[3])
        : "r"(a0), "r"(a1), "r"(a2), "r"(a3), "r"(b0), "r"(b1));
}

// arow: A row (bm + tid>>1), brow: B row (bn + tid>>2); both K-contiguous.
__device__ __forceinline__ void mma_gemm_loop(const float* __restrict__ arow,
                                              const float* __restrict__ brow,
                                              unsigned* As, unsigned* Bs, int tid,
                                              float c[2][4][4]) {
    const int lsegA = (tid & 1) * 16;   // 2 threads per A row, 16 cols each
    const int lsegB = (tid & 3) * 8;    // 4 threads per B row, 8 cols each
    const int arw = tid >> 1;
    const int brw = tid >> 2;
    const int lane = tid & 31;
    const int wid = tid >> 5;
    const int wm = (wid >> 1) * 32;
    const int wn = (wid & 1) * 32;
    const int gr = lane >> 2, tg = lane & 3;
    for (int kt = 0; kt < D_; kt += BK) {
        float4 a[4], b[2];
#pragma unroll
        for (int j = 0; j < 4; j++)
            a[j] = *(const float4*)(arow + kt + lsegA + 4 * j);
#pragma unroll
        for (int j = 0; j < 2; j++)
            b[j] = *(const float4*)(brow + kt + lsegB + 4 * j);
        __syncthreads();
#pragma unroll
        for (int j = 0; j < 4; j++)
            *(uint4*)(As + arw * KSTR + lsegA + 4 * j) =
                make_uint4(f2tf(a[j].x), f2tf(a[j].y), f2tf(a[j].z), f2tf(a[j].w));
#pragma unroll
        for (int j = 0; j < 2; j++)
            *(uint4*)(Bs + brw * KSTR + lsegB + 4 * j) =
                make_uint4(f2tf(b[j].x), f2tf(b[j].y), f2tf(b[j].z), f2tf(b[j].w));
        __syncthreads();
#pragma unroll
        for (int ks = 0; ks < 4; ks++) {
            unsigned af[2][4], bf[4][2];
#pragma unroll
            for (int mi = 0; mi < 2; mi++) {
                const unsigned* ab = As + (wm + mi * 16 + gr) * KSTR + ks * 8 + tg;
                af[mi][0] = ab[0];
                af[mi][1] = ab[8 * KSTR];
                af[mi][2] = ab[4];
                af[mi][3] = ab[8 * KSTR + 4];
            }
#pragma unroll
            for (int ni = 0; ni < 4; ni++) {
                const unsigned* bb = Bs + (wn + ni * 8 + gr) * KSTR + ks * 8 + tg;
                bf[ni][0] = bb[0];
                bf[ni][1] = bb[4];
            }
#pragma unroll
            for (int mi = 0; mi < 2; mi++)
#pragma unroll
                for (int ni = 0; ni < 4; ni++)
                    mma_tf32(c[mi][ni], af[mi][0], af[mi][1], af[mi][2], af[mi][3],
                             bf[ni][0], bf[ni][1]);
        }
    }
}

// query = concat(rc, utt) @ Wq^T + bq -> g_query
__global__ __launch_bounds__(256) void gemm_q_kernel(const float* __restrict__ rc,
                                                     const float* __restrict__ utt,
                                                     const float* __restrict__ W,
                                                     const float* __restrict__ bias) {
    __shared__ __align__(16) unsigned As[BM * KSTR];
    __shared__ __align__(16) unsigned Bs[BN * KSTR];
    const int tid = threadIdx.x;
    const int bm = blockIdx.x * BM, bn = blockIdx.y * BN;
    const int arowi = bm + (tid >> 1);
    const float* arow = (arowi < R_) ? rc + (size_t)arowi * D_
                                     : utt + (size_t)(arowi - R_) * D_;
    const float* brow = W + (size_t)(bn + (tid >> 2)) * D_;
    float c[2][4][4];
#pragma unroll
    for (int a = 0; a < 2; a++)
#pragma unroll
        for (int b = 0; b < 4; b++)
#pragma unroll
            for (int d = 0; d < 4; d++) c[a][b][d] = 0.f;
    mma_gemm_loop(arow, brow, As, Bs, tid, c);
    const int lane = tid & 31;
    const int wid = tid >> 5;
    const int wm = (wid >> 1) * 32, wn = (wid & 1) * 32;
    const int gr = lane >> 2, tg = lane & 3;
#pragma unroll
    for (int ni = 0; ni < 4; ni++) {
        int col = bn + wn + ni * 8 + tg * 2;
        float2 bb = *(const float2*)(bias + col);
#pragma unroll
        for (int mi = 0; mi < 2; mi++) {
            int row = bm + wm + mi * 16 + gr;
            *(float2*)(g_query + (size_t)row * D_ + col) =
                make_float2(c[mi][ni][0] + bb.x, c[mi][ni][1] + bb.y);
            *(float2*)(g_query + (size_t)(row + 8) * D_ + col) =
                make_float2(c[mi][ni][2] + bb.x, c[mi][ni][3] + bb.y);
        }
    }
}

// kv = concat(mem, rc, utt) @ Wkv^T + bkv -> scattered into key/value buffers
__global__ __launch_bounds__(256) void gemm_kv_kernel(const float* __restrict__ mem,
                                                      const float* __restrict__ rc,
                                                      const float* __restrict__ utt,
                                                      const float* __restrict__ W,
                                                      const float* __restrict__ bias,
                                                      float* __restrict__ keyBuf,
                                                      float* __restrict__ valBuf) {
    __shared__ __align__(16) unsigned As[BM * KSTR];
    __shared__ __align__(16) unsigned Bs[BN * KSTR];
    const int tid = threadIdx.x;
    const int bm = blockIdx.x * BM, bn = blockIdx.y * BN;
    const int arowi = bm + (tid >> 1);
    const float* arow = (arowi < M_)      ? mem + (size_t)arowi * D_
                      : (arowi < M_ + R_) ? rc + (size_t)(arowi - M_) * D_
                                          : utt + (size_t)(arowi - M_ - R_) * D_;
    const float* brow = W + (size_t)(bn + (tid >> 2)) * D_;
    float c[2][4][4];
#pragma unroll
    for (int a = 0; a < 2; a++)
#pragma unroll
        for (int b = 0; b < 4; b++)
#pragma unroll
            for (int d = 0; d < 4; d++) c[a][b][d] = 0.f;
    mma_gemm_loop(arow, brow, As, Bs, tid, c);
    const int lane = tid & 31;
    const int wid = tid >> 5;
    const int wm = (wid >> 1) * 32, wn = (wid & 1) * 32;
    const int gr = lane >> 2, tg = lane & 3;
    float* obase = (bn < D_) ? keyBuf : valBuf;
    const int cb = (bn < D_) ? bn : bn - D_;
#pragma unroll
    for (int ni = 0; ni < 4; ni++) {
        int col = cb + wn + ni * 8 + tg * 2;
        float2 bb = *(const float2*)(bias + bn + wn + ni * 8 + tg * 2);
#pragma unroll
        for (int mi = 0; mi < 2; mi++) {
            int row0 = bm + wm + mi * 16 + gr;
            int ro0 = (row0 < M_ + R_) ? row0 : row0 + L_;
            int row1 = row0 + 8;
            int ro1 = (row1 < M_ + R_) ? row1 : row1 + L_;
            *(float2*)(obase + (size_t)ro0 * D_ + col) =
                make_float2(c[mi][ni][0] + bb.x, c[mi][ni][1] + bb.y);
            *(float2*)(obase + (size_t)ro1 * D_ + col) =
                make_float2(c[mi][ni][2] + bb.x, c[mi][ni][3] + bb.y);
        }
    }
}

// out = g_attn @ Wo^T + bo
__global__ __launch_bounds__(256) void gemm_o_kernel(const float* __restrict__ W,
                                                     const float* __restrict__ bias,
                                                     float* __restrict__ outBuf) {
    __shared__ __align__(16) unsigned As[BM * KSTR];
    __shared__ __align__(16) unsigned Bs[BN * KSTR];
    const int tid = threadIdx.x;
    const int bm = blockIdx.x * BM, bn = blockIdx.y * BN;
    const float* arow = g_attn + (size_t)(bm + (tid >> 1)) * D_;
    const float* brow = W + (size_t)(bn + (tid >> 2)) * D_;
    float c[2][4][4];
#pragma unroll
    for (int a = 0; a < 2; a++)
#pragma unroll
        for (int b = 0; b < 4; b++)
#pragma unroll
            for (int d = 0; d < 4; d++) c[a][b][d] = 0.f;
    mma_gemm_loop(arow, brow, As, Bs, tid, c);
    const int lane = tid & 31;
    const int wid = tid >> 5;
    const int wm = (wid >> 1) * 32, wn = (wid & 1) * 32;
    const int gr = lane >> 2, tg = lane & 3;
#pragma unroll
    for (int ni = 0; ni < 4; ni++) {
        int col = bn + wn + ni * 8 + tg * 2;
        float2 bb = *(const float2*)(bias + col);
#pragma unroll
        for (int mi = 0; mi < 2; mi++) {
            int row = bm + wm + mi * 16 + gr;
            *(float2*)(outBuf + (size_t)row * D_ + col) =
                make_float2(c[mi][ni][0] + bb.x, c[mi][ni][1] + bb.y);
            *(float2*)(outBuf + (size_t)(row + 8) * D_ + col) =
                make_float2(c[mi][ni][2] + bb.x, c[mi][ni][3] + bb.y);
        }
    }
}

// ===========================================================================
// Flash attention v6: tf32 tensor-core S and P@V, TQ=256 (K/V reuse 4x).
// Block = 256 q-rows x one head, 512 threads = 16 warps; warp w owns q-rows
// [w*16, w*16+16). kv tile 64. Q held in registers as tf32 A-fragments.
// Smem: Ks[64][68], Vs[64][72], Ps[256][68] = 103 KB -> 1 CTA/SM (16 warps).
// P is warp-local (only __syncwarp between P write and P@V).
// ===========================================================================
#define AT_TQ 256
#define AT_TK 64
#define KS_STR 68   // [n][k] access: bank = 4*gr+tg -> 32 distinct
#define VS_STR 72   // [k][n] access: bank = 8*tg+gr -> 32 distinct

__global__ __launch_bounds__(512, 1) void attn_kernel(const float* __restrict__ Kg,
                                                      const float* __restrict__ Vg) {
    extern __shared__ __align__(16) unsigned smu[];
    unsigned* Ks = smu;                    // [64][KS_STR]
    unsigned* Vs = Ks + AT_TK * KS_STR;    // [64][VS_STR]
    unsigned* Ps = Vs + AT_TK * VS_STR;    // [256][KS_STR]

    const int tid = threadIdx.x;
    const int lane = tid & 31, wid = tid >> 5;
    const int gr = lane >> 2, tg = lane & 3;
    const int wm = wid * 16;               // warp's q-row strip within block
    const int qbase = blockIdx.x * AT_TQ;
    const int hoff = blockIdx.y * HD;
    const int row_lo = qbase + wm + gr;
    const int row_hi = row_lo + 8;

    // Q fragments for the whole kernel (pre-scaled by 1/sqrt(64), tf32)
    unsigned qf[8][4];
#pragma unroll
    for (int ks = 0; ks < 8; ks++) {
        int c = hoff + ks * 8 + tg;
        qf[ks][0] = f2tf(g_query[(size_t)row_lo * D_ + c] * 0.125f);
        qf[ks][1] = f2tf(g_query[(size_t)row_hi * D_ + c] * 0.125f);
        qf[ks][2] = f2tf(g_query[(size_t)row_lo * D_ + c + 4] * 0.125f);
        qf[ks][3] = f2tf(g_query[(size_t)row_hi * D_ + c + 4] * 0.125f);
    }

    float o[8][4];
#pragma unroll
    for (int i = 0; i < 8; i++)
#pragma unroll
        for (int j = 0; j < 4; j++) o[i][j] = 0.f;
    float m_lo = -INFINITY, m_hi = -INFINITY, l_lo = 0.f, l_hi = 0.f;

    for (int kt = 0; kt < KVL; kt += AT_TK) {
        __syncthreads();  // all warps done with prev Ks/Vs
        // Load K, V tiles (64x64 each), convert to tf32; 2 float4/thread/tensor
#pragma unroll
        for (int jj = 0; jj < 2; jj++) {
            int id = jj * 512 + tid;
            int r = id >> 4;
            int dseg = (id & 15) * 4;
            float4 k4 = *(const float4*)(Kg + (size_t)(kt + r) * D_ + hoff + dseg);
            *(uint4*)(Ks + r * KS_STR + dseg) =
                make_uint4(f2tf(k4.x), f2tf(k4.y), f2tf(k4.z), f2tf(k4.w));
            float4 v4 = *(const float4*)(Vg + (size_t)(kt + r) * D_ + hoff + dseg);
            *(uint4*)(Vs + r * VS_STR + dseg) =
                make_uint4(f2tf(v4.x), f2tf(v4.y), f2tf(v4.z), f2tf(v4.w));
        }
        __syncthreads();

        // ---- S = Q @ K^T : warp computes 16 rows x 64 kv cols ----
        float s[8][4];
#pragma unroll
        for (int i = 0; i < 8; i++)
#pragma unroll
            for (int j = 0; j < 4; j++) s[i][j] = 0.f;
#pragma unroll
        for (int ni = 0; ni < 8; ni++) {
            const unsigned* bb = Ks + (ni * 8 + gr) * KS_STR + tg;
#pragma unroll
            for (int ks = 0; ks < 8; ks++) {
                unsigned b0 = bb[ks * 8];
                unsigned b1 = bb[ks * 8 + 4];
                mma_tf32(s[ni], qf[ks][0], qf[ks][1], qf[ks][2], qf[ks][3], b0, b1);
            }
        }

        // ---- online softmax (rows gr and gr+8; stats within quad) ----
        float mt_lo = -INFINITY, mt_hi = -INFINITY;
#pragma unroll
        for (int ni = 0; ni < 8; ni++) {
            mt_lo = fmaxf(mt_lo, fmaxf(s[ni][0], s[ni][1]));
            mt_hi = fmaxf(mt_hi, fmaxf(s[ni][2], s[ni][3]));
        }
        mt_lo = fmaxf(mt_lo, __shfl_xor_sync(0xffffffffu, mt_lo, 1));
        mt_lo = fmaxf(mt_lo, __shfl_xor_sync(0xffffffffu, mt_lo, 2));
        mt_hi = fmaxf(mt_hi, __shfl_xor_sync(0xffffffffu, mt_hi, 1));
        mt_hi = fmaxf(mt_hi, __shfl_xor_sync(0xffffffffu, mt_hi, 2));
        float mnew_lo = fmaxf(m_lo, mt_lo);
        float mnew_hi = fmaxf(m_hi, mt_hi);
        float alpha_lo = __expf(m_lo - mnew_lo);
        float alpha_hi = __expf(m_hi - mnew_hi);
        float sum_lo = 0.f, sum_hi = 0.f;
#pragma unroll
        for (int ni = 0; ni < 8; ni++) {
            s[ni][0] = __expf(s[ni][0] - mnew_lo);
            s[ni][1] = __expf(s[ni][1] - mnew_lo);
            s[ni][2] = __expf(s[ni][2] - mnew_hi);
            s[ni][3] = __expf(s[ni][3] - mnew_hi);
            sum_lo += s[ni][0] + s[ni][1];
            sum_hi += s[ni][2] + s[ni][3];
        }
        sum_lo += __shfl_xor_sync(0xffffffffu, sum_lo, 1);
        sum_lo += __shfl_xor_sync(0xffffffffu, sum_lo, 2);
        sum_hi += __shfl_xor_sync(0xffffffffu, sum_hi, 1);
        sum_hi += __shfl_xor_sync(0xffffffffu, sum_hi, 2);
        l_lo = l_lo * alpha_lo + sum_lo;
        l_hi = l_hi * alpha_hi + sum_hi;
        m_lo = mnew_lo;
        m_hi = mnew_hi;
#pragma unroll
        for (int ni = 0; ni < 8; ni++) {
            o[ni][0] *= alpha_lo; o[ni][1] *= alpha_lo;
            o[ni][2] *= alpha_hi; o[ni][3] *= alpha_hi;
        }

        // ---- write P (warp-local rows) as tf32 ----
#pragma unroll
        for (int ni = 0; ni < 8; ni++) {
            int cc = ni * 8 + 2 * tg;
            *(uint2*)(Ps + (wm + gr) * KS_STR + cc) =
                make_uint2(f2tf(s[ni][0]), f2tf(s[ni][1]));
            *(uint2*)(Ps + (wm + gr + 8) * KS_STR + cc) =
                make_uint2(f2tf(s[ni][2]), f2tf(s[ni][3]));
        }
        __syncwarp();

        // ---- O += P @ V : warp computes 16 rows x 64 dims ----
#pragma unroll
        for (int ks = 0; ks < 8; ks++) {
            const unsigned* pa = Ps + (wm + gr) * KS_STR + ks * 8 + tg;
            unsigned a0 = pa[0];
            unsigned a1 = pa[8 * KS_STR];
            unsigned a2 = pa[4];
            unsigned a3 = pa[8 * KS_STR + 4];
            const unsigned* vb = Vs + (ks * 8 + tg) * VS_STR + gr;
#pragma unroll
            for (int ni = 0; ni < 8; ni++) {
                unsigned b0 = vb[ni * 8];
                unsigned b1 = vb[4 * VS_STR + ni * 8];
                mma_tf32(o[ni], a0, a1, a2, a3, b0, b1);
            }
        }
    }

    // normalize and write
    float inv_lo = 1.0f / l_lo;
    float inv_hi = 1.0f / l_hi;
#pragma unroll
    for (int ni = 0; ni < 8; ni++) {
        int col = hoff + ni * 8 + 2 * tg;
        *(float2*)(g_attn + (size_t)row_lo * D_ + col) =
            make_float2(o[ni][0] * inv_lo, o[ni][1] * inv_lo);
        *(float2*)(g_attn + (size_t)row_hi * D_ + col) =
            make_float2(o[ni][2] * inv_hi, o[ni][3] * inv_hi);
    }
}

#define ATTN_SMEM ((AT_TK * KS_STR + AT_TK * VS_STR + AT_TQ * KS_STR) * (int)sizeof(unsigned))

// ---------------------------------------------------------------------------
extern "C" void kernel_launch(void* const* d_in, const int* in_sizes, int n_in,
                              void* d_out, int out_size) {
    const float* utt = (const float*)d_in[0];
    const float* rc  = (const float*)d_in[1];
    const float* mem = (const float*)d_in[2];
    const float* lck = (const float*)d_in[3];
    const float* lcv = (const float*)d_in[4];
    const float* Wq  = (const float*)d_in[5];
    const float* bq  = (const float*)d_in[6];
    const float* Wkv = (const float*)d_in[7];
    const float* bkv = (const float*)d_in[8];
    const float* Wo  = (const float*)d_in[9];
    const float* bo  = (const float*)d_in[10];

    float* outBuf = (float*)d_out;                       // [2304,1024]
    float* keyBuf = outBuf + (size_t)QL * D_;            // [3840,1024]
    float* valBuf = keyBuf + (size_t)KVL * D_;           // [3840,1024]

    cudaFuncSetAttribute(attn_kernel, cudaFuncAttributeMaxDynamicSharedMemorySize,
                         ATTN_SMEM);

    gemm_q_kernel<<<dim3(QL / BM, D_ / BN), 256>>>(rc, utt, Wq, bq);
    gemm_kv_kernel<<<dim3((M_ + R_ + U_) / BM, 2 * D_ / BN), 256>>>(
        mem, rc, utt, Wkv, bkv, keyBuf, valBuf);
    cudaMemcpyAsync(keyBuf + (size_t)(M_ + R_) * D_, lck,
                    (size_t)L_ * D_ * sizeof(float), cudaMemcpyDeviceToDevice);
    cudaMemcpyAsync(valBuf + (size_t)(M_ + R_) * D_, lcv,
                    (size_t)L_ * D_ * sizeof(float), cudaMemcpyDeviceToDevice);
    attn_kernel<<<dim3(QL / AT_TQ, NH), 512, ATTN_SMEM>>>(keyBuf, valBuf);
    gemm_o_kernel<<<dim3(QL / BM, D_ / BN), 256>>>(Wo, bo, outBuf);
}

// round 13
// speedup vs baseline: 12.8594x; 1.0084x over previous
#include <cuda_runtime.h>
#include <cuda_bf16.h>
#include <math.h>

#define D_   1024
#define U_   2048
#define R_   256
#define L_   1024
#define M_   512
#define QL   2304   // U + R
#define KVL  3840   // M + R + L + U
#define NH   16
#define HD   64

// Scratch
__device__ float g_query[(size_t)QL * D_];
__device__ float g_attn[(size_t)QL * D_];

// Round-to-nearest tf32 in the integer domain: add half-ULP of bit 13.
// Carry propagates into kept mantissa / exponent correctly (IEEE layout).
__device__ __forceinline__ unsigned rnb(float f) {
    return __float_as_uint(f) + 0x1000u;
}
__device__ __forceinline__ uint4 rnb4(float4 v) {
    return make_uint4(rnb(v.x), rnb(v.y), rnb(v.z), rnb(v.w));
}

// ===========================================================================
// tf32 tensor-core GEMM: C(128x64) = A @ B^T (+bias), both row-major K-contig
// 256 threads = 8 warps (4m x 2n), warp tile 32x32, mma.m16n8k8.tf32.
// Operands pre-rounded to tf32-RN via integer add (no cvt instructions).
// ===========================================================================
#define BM 128
#define BN 64
#define BK 32
#define KSTR 36   // smem stride words -> fragment LDS conflict-free

__device__ __forceinline__ void mma_tf32(float c[4], unsigned a0, unsigned a1,
                                         unsigned a2, unsigned a3,
                                         unsigned b0, unsigned b1) {
    asm("mma.sync.aligned.m16n8k8.row.col.f32.tf32.tf32.f32 "
        "{%0,%1,%2,%3}, {%4,%5,%6,%7}, {%8,%9}, {%0,%1,%2,%3};"
        : "+f"(c[0]), "+f"(c[1]), "+f"(c[2]), "+f"(c[3])
        : "r"(a0), "r"(a1), "r"(a2), "r"(a3), "r"(b0), "r"(b1));
}

// arow: A row (bm + tid>>1), brow: B row (bn + tid>>2); both K-contiguous.
__device__ __forceinline__ void mma_gemm_loop(const float* __restrict__ arow,
                                              const float* __restrict__ brow,
                                              unsigned* As, unsigned* Bs, int tid,
                                              float c[2][4][4]) {
    const int lsegA = (tid & 1) * 16;   // 2 threads per A row, 16 cols each
    const int lsegB = (tid & 3) * 8;    // 4 threads per B row, 8 cols each
    const int arw = tid >> 1;
    const int brw = tid >> 2;
    const int lane = tid & 31;
    const int wid = tid >> 5;
    const int wm = (wid >> 1) * 32;
    const int wn = (wid & 1) * 32;
    const int gr = lane >> 2, tg = lane & 3;
    for (int kt = 0; kt < D_; kt += BK) {
        float4 a[4], b[2];
#pragma unroll
        for (int j = 0; j < 4; j++)
            a[j] = *(const float4*)(arow + kt + lsegA + 4 * j);
#pragma unroll
        for (int j = 0; j < 2; j++)
            b[j] = *(const float4*)(brow + kt + lsegB + 4 * j);
        __syncthreads();
#pragma unroll
        for (int j = 0; j < 4; j++)
            *(uint4*)(As + arw * KSTR + lsegA + 4 * j) = rnb4(a[j]);
#pragma unroll
        for (int j = 0; j < 2; j++)
            *(uint4*)(Bs + brw * KSTR + lsegB + 4 * j) = rnb4(b[j]);
        __syncthreads();
#pragma unroll
        for (int ks = 0; ks < 4; ks++) {
            unsigned af[2][4], bf[4][2];
#pragma unroll
            for (int mi = 0; mi < 2; mi++) {
                const unsigned* ab = As + (wm + mi * 16 + gr) * KSTR + ks * 8 + tg;
                af[mi][0] = ab[0];
                af[mi][1] = ab[8 * KSTR];
                af[mi][2] = ab[4];
                af[mi][3] = ab[8 * KSTR + 4];
            }
#pragma unroll
            for (int ni = 0; ni < 4; ni++) {
                const unsigned* bb = Bs + (wn + ni * 8 + gr) * KSTR + ks * 8 + tg;
                bf[ni][0] = bb[0];
                bf[ni][1] = bb[4];
            }
#pragma unroll
            for (int mi = 0; mi < 2; mi++)
#pragma unroll
                for (int ni = 0; ni < 4; ni++)
                    mma_tf32(c[mi][ni], af[mi][0], af[mi][1], af[mi][2], af[mi][3],
                             bf[ni][0], bf[ni][1]);
        }
    }
}

// query = concat(rc, utt) @ Wq^T + bq -> g_query
__global__ __launch_bounds__(256) void gemm_q_kernel(const float* __restrict__ rc,
                                                     const float* __restrict__ utt,
                                                     const float* __restrict__ W,
                                                     const float* __restrict__ bias) {
    __shared__ __align__(16) unsigned As[BM * KSTR];
    __shared__ __align__(16) unsigned Bs[BN * KSTR];
    const int tid = threadIdx.x;
    const int bm = blockIdx.x * BM, bn = blockIdx.y * BN;
    const int arowi = bm + (tid >> 1);
    const float* arow = (arowi < R_) ? rc + (size_t)arowi * D_
                                     : utt + (size_t)(arowi - R_) * D_;
    const float* brow = W + (size_t)(bn + (tid >> 2)) * D_;
    float c[2][4][4];
#pragma unroll
    for (int a = 0; a < 2; a++)
#pragma unroll
        for (int b = 0; b < 4; b++)
#pragma unroll
            for (int d = 0; d < 4; d++) c[a][b][d] = 0.f;
    mma_gemm_loop(arow, brow, As, Bs, tid, c);
    const int lane = tid & 31;
    const int wid = tid >> 5;
    const int wm = (wid >> 1) * 32, wn = (wid & 1) * 32;
    const int gr = lane >> 2, tg = lane & 3;
#pragma unroll
    for (int ni = 0; ni < 4; ni++) {
        int col = bn + wn + ni * 8 + tg * 2;
        float2 bb = *(const float2*)(bias + col);
#pragma unroll
        for (int mi = 0; mi < 2; mi++) {
            int row = bm + wm + mi * 16 + gr;
            *(float2*)(g_query + (size_t)row * D_ + col) =
                make_float2(c[mi][ni][0] + bb.x, c[mi][ni][1] + bb.y);
            *(float2*)(g_query + (size_t)(row + 8) * D_ + col) =
                make_float2(c[mi][ni][2] + bb.x, c[mi][ni][3] + bb.y);
        }
    }
}

// kv = concat(mem, rc, utt) @ Wkv^T + bkv -> scattered into key/value buffers
__global__ __launch_bounds__(256) void gemm_kv_kernel(const float* __restrict__ mem,
                                                      const float* __restrict__ rc,
                                                      const float* __restrict__ utt,
                                                      const float* __restrict__ W,
                                                      const float* __restrict__ bias,
                                                      float* __restrict__ keyBuf,
                                                      float* __restrict__ valBuf) {
    __shared__ __align__(16) unsigned As[BM * KSTR];
    __shared__ __align__(16) unsigned Bs[BN * KSTR];
    const int tid = threadIdx.x;
    const int bm = blockIdx.x * BM, bn = blockIdx.y * BN;
    const int arowi = bm + (tid >> 1);
    const float* arow = (arowi < M_)      ? mem + (size_t)arowi * D_
                      : (arowi < M_ + R_) ? rc + (size_t)(arowi - M_) * D_
                                          : utt + (size_t)(arowi - M_ - R_) * D_;
    const float* brow = W + (size_t)(bn + (tid >> 2)) * D_;
    float c[2][4][4];
#pragma unroll
    for (int a = 0; a < 2; a++)
#pragma unroll
        for (int b = 0; b < 4; b++)
#pragma unroll
            for (int d = 0; d < 4; d++) c[a][b][d] = 0.f;
    mma_gemm_loop(arow, brow, As, Bs, tid, c);
    const int lane = tid & 31;
    const int wid = tid >> 5;
    const int wm = (wid >> 1) * 32, wn = (wid & 1) * 32;
    const int gr = lane >> 2, tg = lane & 3;
    float* obase = (bn < D_) ? keyBuf : valBuf;
    const int cb = (bn < D_) ? bn : bn - D_;
#pragma unroll
    for (int ni = 0; ni < 4; ni++) {
        int col = cb + wn + ni * 8 + tg * 2;
        float2 bb = *(const float2*)(bias + bn + wn + ni * 8 + tg * 2);
#pragma unroll
        for (int mi = 0; mi < 2; mi++) {
            int row0 = bm + wm + mi * 16 + gr;
            int ro0 = (row0 < M_ + R_) ? row0 : row0 + L_;
            int row1 = row0 + 8;
            int ro1 = (row1 < M_ + R_) ? row1 : row1 + L_;
            *(float2*)(obase + (size_t)ro0 * D_ + col) =
                make_float2(c[mi][ni][0] + bb.x, c[mi][ni][1] + bb.y);
            *(float2*)(obase + (size_t)ro1 * D_ + col) =
                make_float2(c[mi][ni][2] + bb.x, c[mi][ni][3] + bb.y);
        }
    }
}

// out = g_attn @ Wo^T + bo
__global__ __launch_bounds__(256) void gemm_o_kernel(const float* __restrict__ W,
                                                     const float* __restrict__ bias,
                                                     float* __restrict__ outBuf) {
    __shared__ __align__(16) unsigned As[BM * KSTR];
    __shared__ __align__(16) unsigned Bs[BN * KSTR];
    const int tid = threadIdx.x;
    const int bm = blockIdx.x * BM, bn = blockIdx.y * BN;
    const float* arow = g_attn + (size_t)(bm + (tid >> 1)) * D_;
    const float* brow = W + (size_t)(bn + (tid >> 2)) * D_;
    float c[2][4][4];
#pragma unroll
    for (int a = 0; a < 2; a++)
#pragma unroll
        for (int b = 0; b < 4; b++)
#pragma unroll
            for (int d = 0; d < 4; d++) c[a][b][d] = 0.f;
    mma_gemm_loop(arow, brow, As, Bs, tid, c);
    const int lane = tid & 31;
    const int wid = tid >> 5;
    const int wm = (wid >> 1) * 32, wn = (wid & 1) * 32;
    const int gr = lane >> 2, tg = lane & 3;
#pragma unroll
    for (int ni = 0; ni < 4; ni++) {
        int col = bn + wn + ni * 8 + tg * 2;
        float2 bb = *(const float2*)(bias + col);
#pragma unroll
        for (int mi = 0; mi < 2; mi++) {
            int row = bm + wm + mi * 16 + gr;
            *(float2*)(outBuf + (size_t)row * D_ + col) =
                make_float2(c[mi][ni][0] + bb.x, c[mi][ni][1] + bb.y);
            *(float2*)(outBuf + (size_t)(row + 8) * D_ + col) =
                make_float2(c[mi][ni][2] + bb.x, c[mi][ni][3] + bb.y);
        }
    }
}

// ===========================================================================
// Flash attention v8: tf32 tensor-core S and P@V, TQ=256, operands rounded
// to tf32-RN via integer add. 512 threads = 16 warps; warp w owns q-rows
// [w*16, w*16+16). kv tile 64.
// Smem: Ks[64][68], Vs[64][72], Ps[256][68] = 103 KB -> 1 CTA/SM (16 warps).
// ===========================================================================
#define AT_TQ 256
#define AT_TK 64
#define KS_STR 68   // [n][k] access: bank = 4*gr+tg -> 32 distinct
#define VS_STR 72   // [k][n] access: bank = 8*tg+gr -> 32 distinct

__global__ __launch_bounds__(512, 1) void attn_kernel(const float* __restrict__ Kg,
                                                      const float* __restrict__ Vg) {
    extern __shared__ __align__(16) unsigned smu[];
    unsigned* Ks = smu;                    // [64][KS_STR]
    unsigned* Vs = Ks + AT_TK * KS_STR;    // [64][VS_STR]
    unsigned* Ps = Vs + AT_TK * VS_STR;    // [256][KS_STR]

    const int tid = threadIdx.x;
    const int lane = tid & 31, wid = tid >> 5;
    const int gr = lane >> 2, tg = lane & 3;
    const int wm = wid * 16;               // warp's q-row strip within block
    const int qbase = blockIdx.x * AT_TQ;
    const int hoff = blockIdx.y * HD;
    const int row_lo = qbase + wm + gr;
    const int row_hi = row_lo + 8;

    // Q fragments for the whole kernel (pre-scaled by 1/sqrt(64); tf32-RN bits)
    unsigned qf[8][4];
#pragma unroll
    for (int ks = 0; ks < 8; ks++) {
        int c = hoff + ks * 8 + tg;
        qf[ks][0] = rnb(g_query[(size_t)row_lo * D_ + c] * 0.125f);
        qf[ks][1] = rnb(g_query[(size_t)row_hi * D_ + c] * 0.125f);
        qf[ks][2] = rnb(g_query[(size_t)row_lo * D_ + c + 4] * 0.125f);
        qf[ks][3] = rnb(g_query[(size_t)row_hi * D_ + c + 4] * 0.125f);
    }

    float o[8][4];
#pragma unroll
    for (int i = 0; i < 8; i++)
#pragma unroll
        for (int j = 0; j < 4; j++) o[i][j] = 0.f;
    float m_lo = -INFINITY, m_hi = -INFINITY, l_lo = 0.f, l_hi = 0.f;

    for (int kt = 0; kt < KVL; kt += AT_TK) {
        __syncthreads();  // all warps done with prev Ks/Vs
        // Load K, V tiles (64x64 each), round to tf32-RN; 2 float4/thread/tensor
#pragma unroll
        for (int jj = 0; jj < 2; jj++) {
            int id = jj * 512 + tid;
            int r = id >> 4;
            int dseg = (id & 15) * 4;
            *(uint4*)(Ks + r * KS_STR + dseg) =
                rnb4(*(const float4*)(Kg + (size_t)(kt + r) * D_ + hoff + dseg));
            *(uint4*)(Vs + r * VS_STR + dseg) =
                rnb4(*(const float4*)(Vg + (size_t)(kt + r) * D_ + hoff + dseg));
        }
        __syncthreads();

        // ---- S = Q @ K^T : warp computes 16 rows x 64 kv cols ----
        float s[8][4];
#pragma unroll
        for (int i = 0; i < 8; i++)
#pragma unroll
            for (int j = 0; j < 4; j++) s[i][j] = 0.f;
#pragma unroll
        for (int ni = 0; ni < 8; ni++) {
            const unsigned* bb = Ks + (ni * 8 + gr) * KS_STR + tg;
#pragma unroll
            for (int ks = 0; ks < 8; ks++) {
                unsigned b0 = bb[ks * 8];
                unsigned b1 = bb[ks * 8 + 4];
                mma_tf32(s[ni], qf[ks][0], qf[ks][1], qf[ks][2], qf[ks][3], b0, b1);
            }
        }

        // ---- online softmax (rows gr and gr+8; stats within quad) ----
        float mt_lo = -INFINITY, mt_hi = -INFINITY;
#pragma unroll
        for (int ni = 0; ni < 8; ni++) {
            mt_lo = fmaxf(mt_lo, fmaxf(s[ni][0], s[ni][1]));
            mt_hi = fmaxf(mt_hi, fmaxf(s[ni][2], s[ni][3]));
        }
        mt_lo = fmaxf(mt_lo, __shfl_xor_sync(0xffffffffu, mt_lo, 1));
        mt_lo = fmaxf(mt_lo, __shfl_xor_sync(0xffffffffu, mt_lo, 2));
        mt_hi = fmaxf(mt_hi, __shfl_xor_sync(0xffffffffu, mt_hi, 1));
        mt_hi = fmaxf(mt_hi, __shfl_xor_sync(0xffffffffu, mt_hi, 2));
        float mnew_lo = fmaxf(m_lo, mt_lo);
        float mnew_hi = fmaxf(m_hi, mt_hi);
        float alpha_lo = __expf(m_lo - mnew_lo);
        float alpha_hi = __expf(m_hi - mnew_hi);
        float sum_lo = 0.f, sum_hi = 0.f;
#pragma unroll
        for (int ni = 0; ni < 8; ni++) {
            s[ni][0] = __expf(s[ni][0] - mnew_lo);
            s[ni][1] = __expf(s[ni][1] - mnew_lo);
            s[ni][2] = __expf(s[ni][2] - mnew_hi);
            s[ni][3] = __expf(s[ni][3] - mnew_hi);
            sum_lo += s[ni][0] + s[ni][1];
            sum_hi += s[ni][2] + s[ni][3];
        }
        sum_lo += __shfl_xor_sync(0xffffffffu, sum_lo, 1);
        sum_lo += __shfl_xor_sync(0xffffffffu, sum_lo, 2);
        sum_hi += __shfl_xor_sync(0xffffffffu, sum_hi, 1);
        sum_hi += __shfl_xor_sync(0xffffffffu, sum_hi, 2);
        l_lo = l_lo * alpha_lo + sum_lo;
        l_hi = l_hi * alpha_hi + sum_hi;
        m_lo = mnew_lo;
        m_hi = mnew_hi;
#pragma unroll
        for (int ni = 0; ni < 8; ni++) {
            o[ni][0] *= alpha_lo; o[ni][1] *= alpha_lo;
            o[ni][2] *= alpha_hi; o[ni][3] *= alpha_hi;
        }

        // ---- write P (warp-local rows), tf32-RN bits ----
#pragma unroll
        for (int ni = 0; ni < 8; ni++) {
            int cc = ni * 8 + 2 * tg;
            *(uint2*)(Ps + (wm + gr) * KS_STR + cc) =
                make_uint2(rnb(s[ni][0]), rnb(s[ni][1]));
            *(uint2*)(Ps + (wm + gr + 8) * KS_STR + cc) =
                make_uint2(rnb(s[ni][2]), rnb(s[ni][3]));
        }
        __syncwarp();

        // ---- O += P @ V : warp computes 16 rows x 64 dims ----
#pragma unroll
        for (int ks = 0; ks < 8; ks++) {
            const unsigned* pa = Ps + (wm + gr) * KS_STR + ks * 8 + tg;
            unsigned a0 = pa[0];
            unsigned a1 = pa[8 * KS_STR];
            unsigned a2 = pa[4];
            unsigned a3 = pa[8 * KS_STR + 4];
            const unsigned* vb = Vs + (ks * 8 + tg) * VS_STR + gr;
#pragma unroll
            for (int ni = 0; ni < 8; ni++) {
                unsigned b0 = vb[ni * 8];
                unsigned b1 = vb[4 * VS_STR + ni * 8];
                mma_tf32(o[ni], a0, a1, a2, a3, b0, b1);
            }
        }
    }

    // normalize and write
    float inv_lo = 1.0f / l_lo;
    float inv_hi = 1.0f / l_hi;
#pragma unroll
    for (int ni = 0; ni < 8; ni++) {
        int col = hoff + ni * 8 + 2 * tg;
        *(float2*)(g_attn + (size_t)row_lo * D_ + col) =
            make_float2(o[ni][0] * inv_lo, o[ni][1] * inv_lo);
        *(float2*)(g_attn + (size_t)row_hi * D_ + col) =
            make_float2(o[ni][2] * inv_hi, o[ni][3] * inv_hi);
    }
}

#define ATTN_SMEM ((AT_TK * KS_STR + AT_TK * VS_STR + AT_TQ * KS_STR) * (int)sizeof(unsigned))

// ---------------------------------------------------------------------------
extern "C" void kernel_launch(void* const* d_in, const int* in_sizes, int n_in,
                              void* d_out, int out_size) {
    const float* utt = (const float*)d_in[0];
    const float* rc  = (const float*)d_in[1];
    const float* mem = (const float*)d_in[2];
    const float* lck = (const float*)d_in[3];
    const float* lcv = (const float*)d_in[4];
    const float* Wq  = (const float*)d_in[5];
    const float* bq  = (const float*)d_in[6];
    const float* Wkv = (const float*)d_in[7];
    const float* bkv = (const float*)d_in[8];
    const float* Wo  = (const float*)d_in[9];
    const float* bo  = (const float*)d_in[10];

    float* outBuf = (float*)d_out;                       // [2304,1024]
    float* keyBuf = outBuf + (size_t)QL * D_;            // [3840,1024]
    float* valBuf = keyBuf + (size_t)KVL * D_;           // [3840,1024]

    cudaFuncSetAttribute(attn_kernel, cudaFuncAttributeMaxDynamicSharedMemorySize,
                         ATTN_SMEM);

    gemm_q_kernel<<<dim3(QL / BM, D_ / BN), 256>>>(rc, utt, Wq, bq);
    gemm_kv_kernel<<<dim3((M_ + R_ + U_) / BM, 2 * D_ / BN), 256>>>(
        mem, rc, utt, Wkv, bkv, keyBuf, valBuf);
    cudaMemcpyAsync(keyBuf + (size_t)(M_ + R_) * D_, lck,
                    (size_t)L_ * D_ * sizeof(float), cudaMemcpyDeviceToDevice);
    cudaMemcpyAsync(valBuf + (size_t)(M_ + R_) * D_, lcv,
                    (size_t)L_ * D_ * sizeof(float), cudaMemcpyDeviceToDevice);
    attn_kernel<<<dim3(QL / AT_TQ, NH), 512, ATTN_SMEM>>>(keyBuf, valBuf);
    gemm_o_kernel<<<dim3(QL / BM, D_ / BN), 256>>>(Wo, bo, outBuf);
}